// round 2
// baseline (speedup 1.0000x reference)
#include <cuda_runtime.h>
#include <math.h>

#define DIM    1024
#define BATCH  4
#define SEQ    8192
#define MTOT   (BATCH * SEQ)      // 32768
#define CHUNK  256
#define NCHUNK (SEQ / CHUNK)      // 32

// Scratch (device globals: allocation-free per harness rules)
__device__ float g_h[MTOT * DIM];                    // in_proj output
__device__ float g_y[MTOT * DIM];                    // scan output
__device__ float g_partial[BATCH * NCHUNK * DIM];    // per-chunk local final states
__device__ float g_carry[BATCH * NCHUNK * DIM];      // inclusive scan of chunk states

// ---------------------------------------------------------------------------
// GEMM (NT): C[m,n] = sum_k A[m,k] * B[n,k] + bias[n]
// A: MxK row-major, B: NxK row-major. M,N multiples of 128; K multiple of 8.
// 128x128 block tile, BK=8, 256 threads, 8x8 per thread in 4 quadrants.
// ---------------------------------------------------------------------------
__global__ __launch_bounds__(256, 2) void sgemm_nt_bias(
    const float* __restrict__ A, const float* __restrict__ B,
    const float* __restrict__ bias, float* __restrict__ C,
    int M, int N, int K)
{
    const int BM = 128, BN = 128, BK = 8;
    __shared__ float As[BK][BM];
    __shared__ float Bs[BK][BN];

    const int tid = threadIdx.x;
    const int bm  = blockIdx.y * BM;
    const int bn  = blockIdx.x * BN;

    // global->smem load mapping: 256 threads x float4 = 1024 floats per tile
    const int lr = tid >> 1;           // row within tile (0..127)
    const int lc = (tid & 1) * 4;      // k-offset (0 or 4)

    // compute mapping: 16x16 threads, 4x4 micro-tiles in 4 quadrants
    const int tx = tid & 15;
    const int ty = tid >> 4;

    const float* Ab = A + bm * K;
    const float* Bb = B + bn * K;

    float acc[8][8];
#pragma unroll
    for (int i = 0; i < 8; i++)
#pragma unroll
        for (int j = 0; j < 8; j++) acc[i][j] = 0.f;

    for (int k0 = 0; k0 < K; k0 += BK) {
        float4 av = *(const float4*)(Ab + lr * K + k0 + lc);
        float4 bv = *(const float4*)(Bb + lr * K + k0 + lc);
        As[lc + 0][lr] = av.x; As[lc + 1][lr] = av.y;
        As[lc + 2][lr] = av.z; As[lc + 3][lr] = av.w;
        Bs[lc + 0][lr] = bv.x; Bs[lc + 1][lr] = bv.y;
        Bs[lc + 2][lr] = bv.z; Bs[lc + 3][lr] = bv.w;
        __syncthreads();

#pragma unroll
        for (int k = 0; k < BK; k++) {
            float4 a0 = *(const float4*)&As[k][ty * 4];
            float4 a1 = *(const float4*)&As[k][64 + ty * 4];
            float4 b0 = *(const float4*)&Bs[k][tx * 4];
            float4 b1 = *(const float4*)&Bs[k][64 + tx * 4];
            float a[8] = {a0.x, a0.y, a0.z, a0.w, a1.x, a1.y, a1.z, a1.w};
            float b[8] = {b0.x, b0.y, b0.z, b0.w, b1.x, b1.y, b1.z, b1.w};
#pragma unroll
            for (int i = 0; i < 8; i++)
#pragma unroll
                for (int j = 0; j < 8; j++)
                    acc[i][j] = fmaf(a[i], b[j], acc[i][j]);
        }
        __syncthreads();
    }

    // epilogue: 4 quadrants, float4 stores
#pragma unroll
    for (int qi = 0; qi < 2; qi++) {
#pragma unroll
        for (int i = 0; i < 4; i++) {
            int row = bm + qi * 64 + ty * 4 + i;
#pragma unroll
            for (int qj = 0; qj < 2; qj++) {
                int col = bn + qj * 64 + tx * 4;
                float4 v;
                v.x = acc[qi * 4 + i][qj * 4 + 0] + bias[col + 0];
                v.y = acc[qi * 4 + i][qj * 4 + 1] + bias[col + 1];
                v.z = acc[qi * 4 + i][qj * 4 + 2] + bias[col + 2];
                v.w = acc[qi * 4 + i][qj * 4 + 3] + bias[col + 3];
                *(float4*)(C + row * N + col) = v;
            }
        }
    }
}

// ---------------------------------------------------------------------------
// Scan stage 1: per-(b, chunk, d) local final state starting from 0.
// ---------------------------------------------------------------------------
__global__ __launch_bounds__(256) void scan_partial(
    const float* __restrict__ h, const float* __restrict__ a,
    const float* __restrict__ bgate, float* __restrict__ partial)
{
    const int d = blockIdx.x * blockDim.x + threadIdx.x;  // 0..1023
    const int c = blockIdx.y;
    const int b = blockIdx.z;
    const float A  = 1.f / (1.f + expf(-a[d]));
    const float bb = bgate[d];

    const float* hp = h + (b * SEQ + c * CHUNK) * DIM + d;
    float s = 0.f;
#pragma unroll 8
    for (int t = 0; t < CHUNK; t++)
        s = fmaf(A, s, bb * hp[t * DIM]);

    partial[(b * NCHUNK + c) * DIM + d] = s;
}

// ---------------------------------------------------------------------------
// Scan stage 2: sequential scan over chunk carries per channel (tiny).
// carry[b][c][d] = exact state after chunk c, given init 0.
// ---------------------------------------------------------------------------
__global__ __launch_bounds__(256) void scan_carries(
    const float* __restrict__ partial, const float* __restrict__ a,
    float* __restrict__ carry)
{
    const int d = blockIdx.x * blockDim.x + threadIdx.x;
    const int b = blockIdx.y;
    const float A = 1.f / (1.f + expf(-a[d]));
    float Ap = A;
#pragma unroll
    for (int i = 0; i < 8; i++) Ap *= Ap;   // A^(2^8) = A^CHUNK

    float s = 0.f;
#pragma unroll
    for (int c = 0; c < NCHUNK; c++) {
        s = fmaf(Ap, s, partial[(b * NCHUNK + c) * DIM + d]);
        carry[(b * NCHUNK + c) * DIM + d] = s;
    }
}

// ---------------------------------------------------------------------------
// Scan stage 3: replay each chunk with correct initial state, write y.
// ---------------------------------------------------------------------------
__global__ __launch_bounds__(256) void scan_apply(
    const float* __restrict__ h, const float* __restrict__ a,
    const float* __restrict__ bgate, const float* __restrict__ carry,
    float* __restrict__ y)
{
    const int d = blockIdx.x * blockDim.x + threadIdx.x;
    const int c = blockIdx.y;
    const int b = blockIdx.z;
    const float A  = 1.f / (1.f + expf(-a[d]));
    const float bb = bgate[d];

    float s = (c == 0) ? 0.f : carry[(b * NCHUNK + (c - 1)) * DIM + d];

    const int off = (b * SEQ + c * CHUNK) * DIM + d;
    const float* hp = h + off;
    float*       yp = y + off;
#pragma unroll 8
    for (int t = 0; t < CHUNK; t++) {
        s = fmaf(A, s, bb * hp[t * DIM]);
        yp[t * DIM] = s;
    }
}

// ---------------------------------------------------------------------------
extern "C" void kernel_launch(void* const* d_in, const int* in_sizes, int n_in,
                              void* d_out, int out_size)
{
    const float* x     = (const float*)d_in[0];
    const float* w_in  = (const float*)d_in[1];
    const float* b_in  = (const float*)d_in[2];
    const float* a     = (const float*)d_in[3];
    const float* bg    = (const float*)d_in[4];
    const float* w_out = (const float*)d_in[5];
    const float* b_out = (const float*)d_in[6];
    float* out = (float*)d_out;

    float *h, *y, *partial, *carry;
    cudaGetSymbolAddress((void**)&h, g_h);
    cudaGetSymbolAddress((void**)&y, g_y);
    cudaGetSymbolAddress((void**)&partial, g_partial);
    cudaGetSymbolAddress((void**)&carry, g_carry);

    // GEMM 1: h = x @ w_in^T + b_in   (M=32768, N=1024, K=1024)
    {
        dim3 grid(DIM / 128, MTOT / 128);
        sgemm_nt_bias<<<grid, 256>>>(x, w_in, b_in, h, MTOT, DIM, DIM);
    }

    // Scan
    {
        dim3 g1(DIM / 256, NCHUNK, BATCH);
        scan_partial<<<g1, 256>>>(h, a, bg, partial);
        dim3 g2(DIM / 256, BATCH);
        scan_carries<<<g2, 256>>>(partial, a, carry);
        dim3 g3(DIM / 256, NCHUNK, BATCH);
        scan_apply<<<g3, 256>>>(h, a, bg, carry, y);
    }

    // GEMM 2: out = y @ w_out^T + b_out
    {
        dim3 grid(DIM / 128, MTOT / 128);
        sgemm_nt_bias<<<grid, 256>>>(y, w_out, b_out, out, MTOT, DIM, DIM);
    }
}

// round 4
// speedup vs baseline: 3.1393x; 3.1393x over previous
#include <cuda_runtime.h>
#include <cuda_bf16.h>
#include <cstdint>
#include <math.h>

#define DIM    1024
#define BATCH  4
#define SEQ    8192
#define MTOT   (BATCH * SEQ)      // 32768
#define CHUNK  256
#define NCHUNK (SEQ / CHUNK)      // 32

// ---------------- scratch (device globals; no allocs allowed) ----------------
__device__ float          g_h[MTOT * DIM];            // in_proj output (fp32)
__device__ __nv_bfloat16  g_ahi[MTOT * DIM];          // x-hi, later y-hi
__device__ __nv_bfloat16  g_alo[MTOT * DIM];          // x-lo, later y-lo
__device__ __nv_bfloat16  g_wihi[DIM * DIM];
__device__ __nv_bfloat16  g_wilo[DIM * DIM];
__device__ __nv_bfloat16  g_wohi[DIM * DIM];
__device__ __nv_bfloat16  g_wolo[DIM * DIM];
__device__ float          g_partial[BATCH * NCHUNK * DIM];
__device__ float          g_carry[BATCH * NCHUNK * DIM];

// ---------------- PTX helpers (base ISA only: sm_80-class features) ----------
__device__ __forceinline__ uint32_t smem_u32(const void* p) {
    uint32_t a;
    asm("{ .reg .u64 t; cvta.to.shared.u64 t, %1; cvt.u32.u64 %0, t; }" : "=r"(a) : "l"(p));
    return a;
}
__device__ __forceinline__ void cp16(uint32_t saddr, const void* gaddr) {
    asm volatile("cp.async.cg.shared.global [%0], [%1], 16;" :: "r"(saddr), "l"(gaddr) : "memory");
}
__device__ __forceinline__ void ldsm4(uint32_t& r0, uint32_t& r1, uint32_t& r2, uint32_t& r3,
                                      uint32_t addr) {
    asm volatile("ldmatrix.sync.aligned.m8n8.x4.shared.b16 {%0,%1,%2,%3}, [%4];"
                 : "=r"(r0), "=r"(r1), "=r"(r2), "=r"(r3) : "r"(addr));
}
__device__ __forceinline__ void mma16816(float* d, const uint32_t* a, const uint32_t* b) {
    asm volatile(
        "mma.sync.aligned.m16n8k16.row.col.f32.bf16.bf16.f32 "
        "{%0,%1,%2,%3}, {%4,%5,%6,%7}, {%8,%9}, {%0,%1,%2,%3};"
        : "+f"(d[0]), "+f"(d[1]), "+f"(d[2]), "+f"(d[3])
        : "r"(a[0]), "r"(a[1]), "r"(a[2]), "r"(a[3]), "r"(b[0]), "r"(b[1]));
}

// ---------------- GEMM: C[m,n] = (Ahi+Alo)[m,:]·(Bhi+Blo)[n,:] + bias[n]
// 3-term bf16 split, fp32 accum. CTA tile 128x128, BK=32, 8 warps (64x32 each),
// 2-stage cp.async pipeline. Smem rows padded to 80B (conflict-free ldmatrix).
// ----------------------------------------------------------------------------
#define GBM 128
#define GBN 128
#define GBK 32
#define KITERS (DIM / GBK)          // 32
#define ROWB   80                   // 32 bf16 = 64B + 16B pad
#define TILE_B (128 * ROWB)         // 10240
#define AHI_O  0
#define ALO_O  (1 * TILE_B)
#define BHI_O  (2 * TILE_B)
#define BLO_O  (3 * TILE_B)
#define STAGE_B (4 * TILE_B)        // 40960
#define GEMM_SMEM (2 * STAGE_B)     // 81920

__device__ __forceinline__ void load_stage(
    uint32_t sstage, const char* a0, const char* a1, const char* a2, const char* a3,
    int kbyte, int tid)
{
    const char* src[4] = {a0, a1, a2, a3};
#pragma unroll
    for (int t = 0; t < 4; t++) {
#pragma unroll
        for (int j = 0; j < 2; j++) {
            int chunk = tid * 2 + j;          // 0..511
            int row = chunk >> 2, c = chunk & 3;
            cp16(sstage + t * TILE_B + row * ROWB + c * 16,
                 src[t] + (size_t)row * 2048 + kbyte + c * 16);
        }
    }
}

__global__ __launch_bounds__(256, 1)
void gemm_bf16x3(const __nv_bfloat16* __restrict__ Ahi, const __nv_bfloat16* __restrict__ Alo,
                 const __nv_bfloat16* __restrict__ Bhi, const __nv_bfloat16* __restrict__ Blo,
                 const float* __restrict__ bias, float* __restrict__ C)
{
    extern __shared__ char smem[];
    const uint32_t sbase = smem_u32(smem);
    const int tid = threadIdx.x, wid = tid >> 5, lane = tid & 31;
    const int bn = blockIdx.x * GBN;
    const int bm = blockIdx.y * GBM;
    const int wm = wid & 1;            // 0..1 -> 64-row slab
    const int wn = wid >> 1;           // 0..3 -> 32-col slab

    const char* pAh = (const char*)Ahi + (size_t)bm * 2048;
    const char* pAl = (const char*)Alo + (size_t)bm * 2048;
    const char* pBh = (const char*)Bhi + (size_t)bn * 2048;
    const char* pBl = (const char*)Blo + (size_t)bn * 2048;

    float acc[4][4][4];
#pragma unroll
    for (int i = 0; i < 4; i++)
#pragma unroll
        for (int j = 0; j < 4; j++)
#pragma unroll
            for (int r = 0; r < 4; r++) acc[i][j][r] = 0.f;

    // per-lane ldmatrix address offsets
    const uint32_t laneA = (uint32_t)(lane & 15) * ROWB + (uint32_t)(lane >> 4) * 16;
    const uint32_t laneB = (uint32_t)((lane & 7) + ((lane >> 4) << 3)) * ROWB
                         + (uint32_t)((lane >> 3) & 1) * 16;

    // prologue: stage 0
    load_stage(sbase, pAh, pAl, pBh, pBl, 0, tid);
    asm volatile("cp.async.commit_group;" ::: "memory");

    for (int i = 0; i < KITERS; i++) {
        if (i + 1 < KITERS) {
            load_stage(sbase + ((i + 1) & 1) * STAGE_B, pAh, pAl, pBh, pBl,
                       (i + 1) * (GBK * 2), tid);
            asm volatile("cp.async.commit_group;" ::: "memory");
            asm volatile("cp.async.wait_group 1;" ::: "memory");
        } else {
            asm volatile("cp.async.wait_group 0;" ::: "memory");
        }
        __syncthreads();

        const uint32_t sg = sbase + (i & 1) * STAGE_B;
        const uint32_t aBase = sg + (uint32_t)wm * 64 * ROWB;
        const uint32_t bBase = sg + (uint32_t)wn * 32 * ROWB;

#pragma unroll
        for (int ks = 0; ks < 2; ks++) {
            uint32_t ah[4][4], al[4][4], bh[4][2], bl[4][2];
#pragma unroll
            for (int mi = 0; mi < 4; mi++) {
                uint32_t ad = aBase + AHI_O + (uint32_t)mi * 16 * ROWB + ks * 32 + laneA;
                ldsm4(ah[mi][0], ah[mi][1], ah[mi][2], ah[mi][3], ad);
            }
#pragma unroll
            for (int mi = 0; mi < 4; mi++) {
                uint32_t ad = aBase + ALO_O + (uint32_t)mi * 16 * ROWB + ks * 32 + laneA;
                ldsm4(al[mi][0], al[mi][1], al[mi][2], al[mi][3], ad);
            }
#pragma unroll
            for (int nj = 0; nj < 2; nj++) {
                uint32_t bd = bBase + BHI_O + (uint32_t)nj * 16 * ROWB + ks * 32 + laneB;
                ldsm4(bh[2 * nj][0], bh[2 * nj][1], bh[2 * nj + 1][0], bh[2 * nj + 1][1], bd);
                uint32_t bd2 = bBase + BLO_O + (uint32_t)nj * 16 * ROWB + ks * 32 + laneB;
                ldsm4(bl[2 * nj][0], bl[2 * nj][1], bl[2 * nj + 1][0], bl[2 * nj + 1][1], bd2);
            }
#pragma unroll
            for (int mi = 0; mi < 4; mi++)
#pragma unroll
                for (int ni = 0; ni < 4; ni++) {
                    mma16816(acc[mi][ni], ah[mi], bh[ni]);
                    mma16816(acc[mi][ni], ah[mi], bl[ni]);
                    mma16816(acc[mi][ni], al[mi], bh[ni]);
                }
        }
        __syncthreads();
    }

    // epilogue: bias + store fp32
#pragma unroll
    for (int mi = 0; mi < 4; mi++) {
        int r0 = bm + wm * 64 + mi * 16 + (lane >> 2);
#pragma unroll
        for (int ni = 0; ni < 4; ni++) {
            int cix = bn + wn * 32 + ni * 8 + (lane & 3) * 2;
            float2 bv = *(const float2*)(bias + cix);
            float2 o0, o1;
            o0.x = acc[mi][ni][0] + bv.x; o0.y = acc[mi][ni][1] + bv.y;
            o1.x = acc[mi][ni][2] + bv.x; o1.y = acc[mi][ni][3] + bv.y;
            *(float2*)(C + (size_t)r0 * DIM + cix) = o0;
            *(float2*)(C + (size_t)(r0 + 8) * DIM + cix) = o1;
        }
    }
}

// ---------------- fp32 -> bf16 hi/lo split ----------------
__global__ __launch_bounds__(256) void split_bf16(
    const float4* __restrict__ in, __nv_bfloat162* __restrict__ hi,
    __nv_bfloat162* __restrict__ lo, int n4)
{
    int i = blockIdx.x * blockDim.x + threadIdx.x;
    if (i >= n4) return;
    float4 v = in[i];
    __nv_bfloat16 h0 = __float2bfloat16(v.x);
    __nv_bfloat16 h1 = __float2bfloat16(v.y);
    __nv_bfloat16 h2 = __float2bfloat16(v.z);
    __nv_bfloat16 h3 = __float2bfloat16(v.w);
    __nv_bfloat16 l0 = __float2bfloat16(v.x - __bfloat162float(h0));
    __nv_bfloat16 l1 = __float2bfloat16(v.y - __bfloat162float(h1));
    __nv_bfloat16 l2 = __float2bfloat16(v.z - __bfloat162float(h2));
    __nv_bfloat16 l3 = __float2bfloat16(v.w - __bfloat162float(h3));
    hi[2 * i + 0] = __nv_bfloat162(h0, h1);
    hi[2 * i + 1] = __nv_bfloat162(h2, h3);
    lo[2 * i + 0] = __nv_bfloat162(l0, l1);
    lo[2 * i + 1] = __nv_bfloat162(l2, l3);
}

// ---------------- scan (3-stage chunked linear recurrence) ----------------
__global__ __launch_bounds__(256) void scan_partial(
    const float* __restrict__ h, const float* __restrict__ a,
    const float* __restrict__ bgate, float* __restrict__ partial)
{
    const int d = blockIdx.x * blockDim.x + threadIdx.x;
    const int c = blockIdx.y;
    const int b = blockIdx.z;
    const float A  = 1.f / (1.f + expf(-a[d]));
    const float bb = bgate[d];
    const float* hp = h + ((size_t)(b * SEQ + c * CHUNK)) * DIM + d;
    float s = 0.f;
#pragma unroll 8
    for (int t = 0; t < CHUNK; t++)
        s = fmaf(A, s, bb * hp[(size_t)t * DIM]);
    partial[(b * NCHUNK + c) * DIM + d] = s;
}

__global__ __launch_bounds__(256) void scan_carries(
    const float* __restrict__ partial, const float* __restrict__ a,
    float* __restrict__ carry)
{
    const int d = blockIdx.x * blockDim.x + threadIdx.x;
    const int b = blockIdx.y;
    const float A = 1.f / (1.f + expf(-a[d]));
    float Ap = A;
#pragma unroll
    for (int i = 0; i < 8; i++) Ap *= Ap;   // A^256
    float s = 0.f;
#pragma unroll
    for (int c = 0; c < NCHUNK; c++) {
        s = fmaf(Ap, s, partial[(b * NCHUNK + c) * DIM + d]);
        carry[(b * NCHUNK + c) * DIM + d] = s;
    }
}

__global__ __launch_bounds__(256) void scan_apply(
    const float* __restrict__ h, const float* __restrict__ a,
    const float* __restrict__ bgate, const float* __restrict__ carry,
    __nv_bfloat16* __restrict__ yhi, __nv_bfloat16* __restrict__ ylo)
{
    const int d = blockIdx.x * blockDim.x + threadIdx.x;
    const int c = blockIdx.y;
    const int b = blockIdx.z;
    const float A  = 1.f / (1.f + expf(-a[d]));
    const float bb = bgate[d];

    float s = (c == 0) ? 0.f : carry[(b * NCHUNK + (c - 1)) * DIM + d];

    const size_t off = (size_t)(b * SEQ + c * CHUNK) * DIM + d;
    const float* hp = h + off;
#pragma unroll 8
    for (int t = 0; t < CHUNK; t++) {
        s = fmaf(A, s, bb * hp[(size_t)t * DIM]);
        __nv_bfloat16 hv = __float2bfloat16(s);
        yhi[off + (size_t)t * DIM] = hv;
        ylo[off + (size_t)t * DIM] = __float2bfloat16(s - __bfloat162float(hv));
    }
}

// ---------------------------------------------------------------------------
extern "C" void kernel_launch(void* const* d_in, const int* in_sizes, int n_in,
                              void* d_out, int out_size)
{
    const float* x     = (const float*)d_in[0];
    const float* w_in  = (const float*)d_in[1];
    const float* b_in  = (const float*)d_in[2];
    const float* a     = (const float*)d_in[3];
    const float* bg    = (const float*)d_in[4];
    const float* w_out = (const float*)d_in[5];
    const float* b_out = (const float*)d_in[6];
    float* out = (float*)d_out;

    float *h, *partial, *carry;
    __nv_bfloat16 *ahi, *alo, *wihi, *wilo, *wohi, *wolo;
    cudaGetSymbolAddress((void**)&h, g_h);
    cudaGetSymbolAddress((void**)&ahi, g_ahi);
    cudaGetSymbolAddress((void**)&alo, g_alo);
    cudaGetSymbolAddress((void**)&wihi, g_wihi);
    cudaGetSymbolAddress((void**)&wilo, g_wilo);
    cudaGetSymbolAddress((void**)&wohi, g_wohi);
    cudaGetSymbolAddress((void**)&wolo, g_wolo);
    cudaGetSymbolAddress((void**)&partial, g_partial);
    cudaGetSymbolAddress((void**)&carry, g_carry);

    cudaFuncSetAttribute(gemm_bf16x3, cudaFuncAttributeMaxDynamicSharedMemorySize, GEMM_SMEM);

    // split x and weights to bf16 hi/lo
    {
        int n4 = MTOT * DIM / 4;
        split_bf16<<<n4 / 256, 256>>>((const float4*)x, (__nv_bfloat162*)ahi,
                                      (__nv_bfloat162*)alo, n4);
        int w4 = DIM * DIM / 4;
        split_bf16<<<w4 / 256, 256>>>((const float4*)w_in, (__nv_bfloat162*)wihi,
                                      (__nv_bfloat162*)wilo, w4);
        split_bf16<<<w4 / 256, 256>>>((const float4*)w_out, (__nv_bfloat162*)wohi,
                                      (__nv_bfloat162*)wolo, w4);
    }

    // GEMM 1: h = x @ w_in^T + b_in
    {
        dim3 grid(DIM / GBN, MTOT / GBM);
        gemm_bf16x3<<<grid, 256, GEMM_SMEM>>>(ahi, alo, wihi, wilo, b_in, h);
    }

    // scan; scan_apply writes the bf16 split of y into ahi/alo
    {
        dim3 g1(DIM / 256, NCHUNK, BATCH);
        scan_partial<<<g1, 256>>>(h, a, bg, partial);
        dim3 g2(DIM / 256, BATCH);
        scan_carries<<<g2, 256>>>(partial, a, carry);
        dim3 g3(DIM / 256, NCHUNK, BATCH);
        scan_apply<<<g3, 256>>>(h, a, bg, carry, ahi, alo);
    }

    // GEMM 2: out = y @ w_out^T + b_out
    {
        dim3 grid(DIM / GBN, MTOT / GBM);
        gemm_bf16x3<<<grid, 256, GEMM_SMEM>>>(ahi, alo, wohi, wolo, b_out, out);
    }
}

// round 5
// speedup vs baseline: 3.2331x; 1.0299x over previous
#include <cuda_runtime.h>
#include <cuda_bf16.h>
#include <cstdint>
#include <math.h>

#define DIM    1024
#define BATCH  4
#define SEQ    8192
#define MTOT   (BATCH * SEQ)      // 32768
#define CHUNK  256
#define NCHUNK (SEQ / CHUNK)      // 32

// ---------------- scratch (device globals; no allocs allowed) ----------------
__device__ float          g_h[MTOT * DIM];            // in_proj output (fp32)
__device__ __nv_bfloat16  g_ahi[MTOT * DIM];          // x-hi, later y-hi
__device__ __nv_bfloat16  g_alo[MTOT * DIM];          // x-lo, later y-lo
__device__ __nv_bfloat16  g_wihi[DIM * DIM];
__device__ __nv_bfloat16  g_wilo[DIM * DIM];
__device__ __nv_bfloat16  g_wohi[DIM * DIM];
__device__ __nv_bfloat16  g_wolo[DIM * DIM];
__device__ float          g_partial[BATCH * NCHUNK * DIM];
__device__ float          g_carry[BATCH * NCHUNK * DIM];

// ---------------- PTX helpers (base ISA only) ----------
__device__ __forceinline__ uint32_t smem_u32(const void* p) {
    uint32_t a;
    asm("{ .reg .u64 t; cvta.to.shared.u64 t, %1; cvt.u32.u64 %0, t; }" : "=r"(a) : "l"(p));
    return a;
}
__device__ __forceinline__ void cp16(uint32_t saddr, const void* gaddr) {
    asm volatile("cp.async.cg.shared.global [%0], [%1], 16;" :: "r"(saddr), "l"(gaddr) : "memory");
}
__device__ __forceinline__ void ldsm4(uint32_t& r0, uint32_t& r1, uint32_t& r2, uint32_t& r3,
                                      uint32_t addr) {
    asm volatile("ldmatrix.sync.aligned.m8n8.x4.shared.b16 {%0,%1,%2,%3}, [%4];"
                 : "=r"(r0), "=r"(r1), "=r"(r2), "=r"(r3) : "r"(addr));
}
__device__ __forceinline__ void mma16816(float* d, const uint32_t* a, const uint32_t* b) {
    asm volatile(
        "mma.sync.aligned.m16n8k16.row.col.f32.bf16.bf16.f32 "
        "{%0,%1,%2,%3}, {%4,%5,%6,%7}, {%8,%9}, {%0,%1,%2,%3};"
        : "+f"(d[0]), "+f"(d[1]), "+f"(d[2]), "+f"(d[3])
        : "r"(a[0]), "r"(a[1]), "r"(a[2]), "r"(a[3]), "r"(b[0]), "r"(b[1]));
}

// ---------------- GEMM: C[m,n] = (Ahi+Alo)[m,:]·(Bhi+Blo)[n,:] + bias[n]
// 3-term bf16 split, fp32 accum. CTA tile 128x128, BK=32, 8 warps (64x32 each),
// 3-stage cp.async pipeline, ONE syncthreads per k-iter, fragment prefetch.
// Smem rows padded to 80B (conflict-free ldmatrix).
// ----------------------------------------------------------------------------
#define GBM 128
#define GBN 128
#define GBK 32
#define KITERS (DIM / GBK)          // 32
#define ROWB   80                   // 32 bf16 = 64B + 16B pad
#define TILE_B (128 * ROWB)         // 10240
#define AHI_O  0
#define ALO_O  (1 * TILE_B)
#define BHI_O  (2 * TILE_B)
#define BLO_O  (3 * TILE_B)
#define STAGE_B (4 * TILE_B)        // 40960
#define NSTAGE 3
#define GEMM_SMEM (NSTAGE * STAGE_B)  // 122880

__device__ __forceinline__ void load_stage(
    uint32_t sstage, const char* a0, const char* a1, const char* a2, const char* a3,
    int kbyte, int tid)
{
    const char* src[4] = {a0, a1, a2, a3};
#pragma unroll
    for (int t = 0; t < 4; t++) {
#pragma unroll
        for (int j = 0; j < 2; j++) {
            int chunk = tid * 2 + j;          // 0..511
            int row = chunk >> 2, c = chunk & 3;
            cp16(sstage + t * TILE_B + row * ROWB + c * 16,
                 src[t] + (size_t)row * 2048 + kbyte + c * 16);
        }
    }
}

struct Frags {
    uint32_t ah[4][4];
    uint32_t al[4][4];
    uint32_t bh[4][2];
    uint32_t bl[4][2];
};

__device__ __forceinline__ void load_frags(Frags& f, uint32_t aBase, uint32_t bBase,
                                           int ks, uint32_t laneA, uint32_t laneB)
{
#pragma unroll
    for (int mi = 0; mi < 4; mi++) {
        uint32_t ad = aBase + AHI_O + (uint32_t)mi * 16 * ROWB + ks * 32 + laneA;
        ldsm4(f.ah[mi][0], f.ah[mi][1], f.ah[mi][2], f.ah[mi][3], ad);
    }
#pragma unroll
    for (int mi = 0; mi < 4; mi++) {
        uint32_t ad = aBase + ALO_O + (uint32_t)mi * 16 * ROWB + ks * 32 + laneA;
        ldsm4(f.al[mi][0], f.al[mi][1], f.al[mi][2], f.al[mi][3], ad);
    }
#pragma unroll
    for (int nj = 0; nj < 2; nj++) {
        uint32_t bd = bBase + BHI_O + (uint32_t)nj * 16 * ROWB + ks * 32 + laneB;
        ldsm4(f.bh[2 * nj][0], f.bh[2 * nj][1], f.bh[2 * nj + 1][0], f.bh[2 * nj + 1][1], bd);
        uint32_t bd2 = bBase + BLO_O + (uint32_t)nj * 16 * ROWB + ks * 32 + laneB;
        ldsm4(f.bl[2 * nj][0], f.bl[2 * nj][1], f.bl[2 * nj + 1][0], f.bl[2 * nj + 1][1], bd2);
    }
}

__device__ __forceinline__ void mma_frags(float acc[4][4][4], const Frags& f)
{
#pragma unroll
    for (int mi = 0; mi < 4; mi++)
#pragma unroll
        for (int ni = 0; ni < 4; ni++) {
            mma16816(acc[mi][ni], f.ah[mi], f.bh[ni]);
            mma16816(acc[mi][ni], f.ah[mi], f.bl[ni]);
            mma16816(acc[mi][ni], f.al[mi], f.bh[ni]);
        }
}

__global__ __launch_bounds__(256, 1)
void gemm_bf16x3(const __nv_bfloat16* __restrict__ Ahi, const __nv_bfloat16* __restrict__ Alo,
                 const __nv_bfloat16* __restrict__ Bhi, const __nv_bfloat16* __restrict__ Blo,
                 const float* __restrict__ bias, float* __restrict__ C)
{
    extern __shared__ char smem[];
    const uint32_t sbase = smem_u32(smem);
    const int tid = threadIdx.x, wid = tid >> 5, lane = tid & 31;
    const int bn = blockIdx.x * GBN;
    const int bm = blockIdx.y * GBM;
    const int wm = wid & 1;            // 0..1 -> 64-row slab
    const int wn = wid >> 1;           // 0..3 -> 32-col slab

    const char* pAh = (const char*)Ahi + (size_t)bm * 2048;
    const char* pAl = (const char*)Alo + (size_t)bm * 2048;
    const char* pBh = (const char*)Bhi + (size_t)bn * 2048;
    const char* pBl = (const char*)Blo + (size_t)bn * 2048;

    float acc[4][4][4];
#pragma unroll
    for (int i = 0; i < 4; i++)
#pragma unroll
        for (int j = 0; j < 4; j++)
#pragma unroll
            for (int r = 0; r < 4; r++) acc[i][j][r] = 0.f;

    const uint32_t laneA = (uint32_t)(lane & 15) * ROWB + (uint32_t)(lane >> 4) * 16;
    const uint32_t laneB = (uint32_t)((lane & 7) + ((lane >> 4) << 3)) * ROWB
                         + (uint32_t)((lane >> 3) & 1) * 16;

    // prologue: stages 0 and 1
    load_stage(sbase + 0 * STAGE_B, pAh, pAl, pBh, pBl, 0, tid);
    asm volatile("cp.async.commit_group;" ::: "memory");
    load_stage(sbase + 1 * STAGE_B, pAh, pAl, pBh, pBl, GBK * 2, tid);
    asm volatile("cp.async.commit_group;" ::: "memory");

    int slot = 0;
    for (int i = 0; i < KITERS; i++) {
        if (i + 1 < KITERS)
            asm volatile("cp.async.wait_group 1;" ::: "memory");
        else
            asm volatile("cp.async.wait_group 0;" ::: "memory");
        __syncthreads();

        if (i + 2 < KITERS) {
            int ws = slot + 2; if (ws >= NSTAGE) ws -= NSTAGE;
            load_stage(sbase + ws * STAGE_B, pAh, pAl, pBh, pBl, (i + 2) * (GBK * 2), tid);
            asm volatile("cp.async.commit_group;" ::: "memory");
        }

        const uint32_t sg = sbase + slot * STAGE_B;
        const uint32_t aBase = sg + (uint32_t)wm * 64 * ROWB;
        const uint32_t bBase = sg + (uint32_t)wn * 32 * ROWB;

        // fragment double buffer across the two k-steps
        Frags f0, f1;
        load_frags(f0, aBase, bBase, 0, laneA, laneB);
        load_frags(f1, aBase, bBase, 1, laneA, laneB);
        mma_frags(acc, f0);
        mma_frags(acc, f1);

        if (++slot == NSTAGE) slot = 0;
    }

    // epilogue: bias + store fp32
#pragma unroll
    for (int mi = 0; mi < 4; mi++) {
        int r0 = bm + wm * 64 + mi * 16 + (lane >> 2);
#pragma unroll
        for (int ni = 0; ni < 4; ni++) {
            int cix = bn + wn * 32 + ni * 8 + (lane & 3) * 2;
            float2 bv = *(const float2*)(bias + cix);
            float2 o0, o1;
            o0.x = acc[mi][ni][0] + bv.x; o0.y = acc[mi][ni][1] + bv.y;
            o1.x = acc[mi][ni][2] + bv.x; o1.y = acc[mi][ni][3] + bv.y;
            *(float2*)(C + (size_t)r0 * DIM + cix) = o0;
            *(float2*)(C + (size_t)(r0 + 8) * DIM + cix) = o1;
        }
    }
}

// ---------------- fp32 -> bf16 hi/lo split ----------------
__global__ __launch_bounds__(256) void split_bf16(
    const float4* __restrict__ in, __nv_bfloat162* __restrict__ hi,
    __nv_bfloat162* __restrict__ lo, int n4)
{
    int i = blockIdx.x * blockDim.x + threadIdx.x;
    if (i >= n4) return;
    float4 v = in[i];
    __nv_bfloat16 h0 = __float2bfloat16(v.x);
    __nv_bfloat16 h1 = __float2bfloat16(v.y);
    __nv_bfloat16 h2 = __float2bfloat16(v.z);
    __nv_bfloat16 h3 = __float2bfloat16(v.w);
    __nv_bfloat16 l0 = __float2bfloat16(v.x - __bfloat162float(h0));
    __nv_bfloat16 l1 = __float2bfloat16(v.y - __bfloat162float(h1));
    __nv_bfloat16 l2 = __float2bfloat16(v.z - __bfloat162float(h2));
    __nv_bfloat16 l3 = __float2bfloat16(v.w - __bfloat162float(h3));
    hi[2 * i + 0] = __nv_bfloat162(h0, h1);
    hi[2 * i + 1] = __nv_bfloat162(h2, h3);
    lo[2 * i + 0] = __nv_bfloat162(l0, l1);
    lo[2 * i + 1] = __nv_bfloat162(l2, l3);
}

// ---------------- scan (3-stage chunked linear recurrence) ----------------
__global__ __launch_bounds__(256) void scan_partial(
    const float* __restrict__ h, const float* __restrict__ a,
    const float* __restrict__ bgate, float* __restrict__ partial)
{
    const int d = blockIdx.x * blockDim.x + threadIdx.x;
    const int c = blockIdx.y;
    const int b = blockIdx.z;
    const float A  = 1.f / (1.f + expf(-a[d]));
    const float bb = bgate[d];
    const float* hp = h + ((size_t)(b * SEQ + c * CHUNK)) * DIM + d;
    float s = 0.f;
#pragma unroll 8
    for (int t = 0; t < CHUNK; t++)
        s = fmaf(A, s, bb * hp[(size_t)t * DIM]);
    partial[(b * NCHUNK + c) * DIM + d] = s;
}

__global__ __launch_bounds__(256) void scan_carries(
    const float* __restrict__ partial, const float* __restrict__ a,
    float* __restrict__ carry)
{
    const int d = blockIdx.x * blockDim.x + threadIdx.x;
    const int b = blockIdx.y;
    const float A = 1.f / (1.f + expf(-a[d]));
    float Ap = A;
#pragma unroll
    for (int i = 0; i < 8; i++) Ap *= Ap;   // A^256
    float s = 0.f;
#pragma unroll
    for (int c = 0; c < NCHUNK; c++) {
        s = fmaf(Ap, s, partial[(b * NCHUNK + c) * DIM + d]);
        carry[(b * NCHUNK + c) * DIM + d] = s;
    }
}

__global__ __launch_bounds__(256) void scan_apply(
    const float* __restrict__ h, const float* __restrict__ a,
    const float* __restrict__ bgate, const float* __restrict__ carry,
    __nv_bfloat16* __restrict__ yhi, __nv_bfloat16* __restrict__ ylo)
{
    const int d = blockIdx.x * blockDim.x + threadIdx.x;
    const int c = blockIdx.y;
    const int b = blockIdx.z;
    const float A  = 1.f / (1.f + expf(-a[d]));
    const float bb = bgate[d];

    float s = (c == 0) ? 0.f : carry[(b * NCHUNK + (c - 1)) * DIM + d];

    const size_t off = (size_t)(b * SEQ + c * CHUNK) * DIM + d;
    const float* hp = h + off;
#pragma unroll 8
    for (int t = 0; t < CHUNK; t++) {
        s = fmaf(A, s, bb * hp[(size_t)t * DIM]);
        __nv_bfloat16 hv = __float2bfloat16(s);
        yhi[off + (size_t)t * DIM] = hv;
        ylo[off + (size_t)t * DIM] = __float2bfloat16(s - __bfloat162float(hv));
    }
}

// ---------------------------------------------------------------------------
extern "C" void kernel_launch(void* const* d_in, const int* in_sizes, int n_in,
                              void* d_out, int out_size)
{
    const float* x     = (const float*)d_in[0];
    const float* w_in  = (const float*)d_in[1];
    const float* b_in  = (const float*)d_in[2];
    const float* a     = (const float*)d_in[3];
    const float* bg    = (const float*)d_in[4];
    const float* w_out = (const float*)d_in[5];
    const float* b_out = (const float*)d_in[6];
    float* out = (float*)d_out;

    float *h, *partial, *carry;
    __nv_bfloat16 *ahi, *alo, *wihi, *wilo, *wohi, *wolo;
    cudaGetSymbolAddress((void**)&h, g_h);
    cudaGetSymbolAddress((void**)&ahi, g_ahi);
    cudaGetSymbolAddress((void**)&alo, g_alo);
    cudaGetSymbolAddress((void**)&wihi, g_wihi);
    cudaGetSymbolAddress((void**)&wilo, g_wilo);
    cudaGetSymbolAddress((void**)&wohi, g_wohi);
    cudaGetSymbolAddress((void**)&wolo, g_wolo);
    cudaGetSymbolAddress((void**)&partial, g_partial);
    cudaGetSymbolAddress((void**)&carry, g_carry);

    cudaFuncSetAttribute(gemm_bf16x3, cudaFuncAttributeMaxDynamicSharedMemorySize, GEMM_SMEM);

    // split x and weights to bf16 hi/lo
    {
        int n4 = MTOT * DIM / 4;
        split_bf16<<<n4 / 256, 256>>>((const float4*)x, (__nv_bfloat162*)ahi,
                                      (__nv_bfloat162*)alo, n4);
        int w4 = DIM * DIM / 4;
        split_bf16<<<w4 / 256, 256>>>((const float4*)w_in, (__nv_bfloat162*)wihi,
                                      (__nv_bfloat162*)wilo, w4);
        split_bf16<<<w4 / 256, 256>>>((const float4*)w_out, (__nv_bfloat162*)wohi,
                                      (__nv_bfloat162*)wolo, w4);
    }

    // GEMM 1: h = x @ w_in^T + b_in
    {
        dim3 grid(DIM / GBN, MTOT / GBM);
        gemm_bf16x3<<<grid, 256, GEMM_SMEM>>>(ahi, alo, wihi, wilo, b_in, h);
    }

    // scan; scan_apply writes the bf16 split of y into ahi/alo
    {
        dim3 g1(DIM / 256, NCHUNK, BATCH);
        scan_partial<<<g1, 256>>>(h, a, bg, partial);
        dim3 g2(DIM / 256, BATCH);
        scan_carries<<<g2, 256>>>(partial, a, carry);
        dim3 g3(DIM / 256, NCHUNK, BATCH);
        scan_apply<<<g3, 256>>>(h, a, bg, carry, ahi, alo);
    }

    // GEMM 2: out = y @ w_out^T + b_out
    {
        dim3 grid(DIM / GBN, MTOT / GBM);
        gemm_bf16x3<<<grid, 256, GEMM_SMEM>>>(ahi, alo, wohi, wolo, b_out, out);
    }
}

// round 6
// speedup vs baseline: 3.5271x; 1.0909x over previous
#include <cuda_runtime.h>
#include <cuda_bf16.h>
#include <cstdint>
#include <math.h>

#define DIM    1024
#define BATCH  4
#define SEQ    8192
#define MTOT   (BATCH * SEQ)      // 32768
#define CHUNK  256
#define NCHUNK (SEQ / CHUNK)      // 32

// ---------------- scratch (device globals; no allocs allowed) ----------------
__device__ float          g_h[MTOT * DIM];            // in_proj output (fp32)
__device__ __nv_bfloat16  g_ahi[MTOT * DIM];          // x-hi, later y-hi
__device__ __nv_bfloat16  g_alo[MTOT * DIM];          // x-lo, later y-lo
__device__ __nv_bfloat16  g_wihi[DIM * DIM];
__device__ __nv_bfloat16  g_wilo[DIM * DIM];
__device__ __nv_bfloat16  g_wohi[DIM * DIM];
__device__ __nv_bfloat16  g_wolo[DIM * DIM];
__device__ float          g_partial[BATCH * NCHUNK * DIM];
__device__ float          g_carry[BATCH * NCHUNK * DIM];

// ---------------- PTX helpers (base ISA only) ----------
__device__ __forceinline__ uint32_t smem_u32(const void* p) {
    uint32_t a;
    asm("{ .reg .u64 t; cvta.to.shared.u64 t, %1; cvt.u32.u64 %0, t; }" : "=r"(a) : "l"(p));
    return a;
}
__device__ __forceinline__ void cp16(uint32_t saddr, const void* gaddr) {
    asm volatile("cp.async.cg.shared.global [%0], [%1], 16;" :: "r"(saddr), "l"(gaddr) : "memory");
}
__device__ __forceinline__ void ldsm4(uint32_t& r0, uint32_t& r1, uint32_t& r2, uint32_t& r3,
                                      uint32_t addr) {
    asm volatile("ldmatrix.sync.aligned.m8n8.x4.shared.b16 {%0,%1,%2,%3}, [%4];"
                 : "=r"(r0), "=r"(r1), "=r"(r2), "=r"(r3) : "r"(addr));
}
__device__ __forceinline__ void mma16816(float* d, const uint32_t* a, const uint32_t* b) {
    asm volatile(
        "mma.sync.aligned.m16n8k16.row.col.f32.bf16.bf16.f32 "
        "{%0,%1,%2,%3}, {%4,%5,%6,%7}, {%8,%9}, {%0,%1,%2,%3};"
        : "+f"(d[0]), "+f"(d[1]), "+f"(d[2]), "+f"(d[3])
        : "r"(a[0]), "r"(a[1]), "r"(a[2]), "r"(a[3]), "r"(b[0]), "r"(b[1]));
}

// ---------------- GEMM: C[m,n] = (Ahi+Alo)[m,:]·(Bhi+Blo)[n,:] + bias[n]
// 3-term bf16 split, fp32 accum. CTA tile 128x128, BK=32, 16 warps (32x32 each),
// 3-stage cp.async pipeline, one syncthreads per k-iter, term-outer MMA order.
// Smem rows padded to 80B (conflict-free ldmatrix).
// ----------------------------------------------------------------------------
#define GBM 128
#define GBN 128
#define GBK 32
#define KITERS (DIM / GBK)          // 32
#define ROWB   80                   // 32 bf16 = 64B + 16B pad
#define TILE_B (128 * ROWB)         // 10240
#define AHI_O  0
#define ALO_O  (1 * TILE_B)
#define BHI_O  (2 * TILE_B)
#define BLO_O  (3 * TILE_B)
#define STAGE_B (4 * TILE_B)        // 40960
#define NSTAGE 3
#define GEMM_SMEM (NSTAGE * STAGE_B)  // 122880
#define NTHREADS 512

__device__ __forceinline__ void load_stage(
    uint32_t sstage, const char* a0, const char* a1, const char* a2, const char* a3,
    int kbyte, int tid)
{
    const char* src[4] = {a0, a1, a2, a3};
    const int row = tid >> 2, c = tid & 3;   // 512 threads = 128 rows x 4 chunks
#pragma unroll
    for (int t = 0; t < 4; t++) {
        cp16(sstage + t * TILE_B + row * ROWB + c * 16,
             src[t] + (size_t)row * 2048 + kbyte + c * 16);
    }
}

__global__ __launch_bounds__(NTHREADS, 1)
void gemm_bf16x3(const __nv_bfloat16* __restrict__ Ahi, const __nv_bfloat16* __restrict__ Alo,
                 const __nv_bfloat16* __restrict__ Bhi, const __nv_bfloat16* __restrict__ Blo,
                 const float* __restrict__ bias, float* __restrict__ C)
{
    extern __shared__ char smem[];
    const uint32_t sbase = smem_u32(smem);
    const int tid = threadIdx.x, wid = tid >> 5, lane = tid & 31;
    const int bn = blockIdx.x * GBN;
    const int bm = blockIdx.y * GBM;
    const int wm = wid & 3;            // 0..3 -> 32-row slab
    const int wn = wid >> 2;           // 0..3 -> 32-col slab

    const char* pAh = (const char*)Ahi + (size_t)bm * 2048;
    const char* pAl = (const char*)Alo + (size_t)bm * 2048;
    const char* pBh = (const char*)Bhi + (size_t)bn * 2048;
    const char* pBl = (const char*)Blo + (size_t)bn * 2048;

    float acc[2][4][4];
#pragma unroll
    for (int i = 0; i < 2; i++)
#pragma unroll
        for (int j = 0; j < 4; j++)
#pragma unroll
            for (int r = 0; r < 4; r++) acc[i][j][r] = 0.f;

    const uint32_t laneA = (uint32_t)(lane & 15) * ROWB + (uint32_t)(lane >> 4) * 16;
    const uint32_t laneB = (uint32_t)((lane & 7) + ((lane >> 4) << 3)) * ROWB
                         + (uint32_t)((lane >> 3) & 1) * 16;

    // prologue: stages 0 and 1
    load_stage(sbase + 0 * STAGE_B, pAh, pAl, pBh, pBl, 0, tid);
    asm volatile("cp.async.commit_group;" ::: "memory");
    load_stage(sbase + 1 * STAGE_B, pAh, pAl, pBh, pBl, GBK * 2, tid);
    asm volatile("cp.async.commit_group;" ::: "memory");

    int slot = 0;
    for (int i = 0; i < KITERS; i++) {
        if (i + 1 < KITERS)
            asm volatile("cp.async.wait_group 1;" ::: "memory");
        else
            asm volatile("cp.async.wait_group 0;" ::: "memory");
        __syncthreads();

        if (i + 2 < KITERS) {
            int ws = slot + 2; if (ws >= NSTAGE) ws -= NSTAGE;
            load_stage(sbase + ws * STAGE_B, pAh, pAl, pBh, pBl, (i + 2) * (GBK * 2), tid);
            asm volatile("cp.async.commit_group;" ::: "memory");
        }

        const uint32_t sg = sbase + slot * STAGE_B;
        const uint32_t aBase = sg + (uint32_t)wm * 32 * ROWB;
        const uint32_t bBase = sg + (uint32_t)wn * 32 * ROWB;

#pragma unroll
        for (int ks = 0; ks < 2; ks++) {
            uint32_t ah[2][4], al[2][4], bh[4][2], bl[4][2];
#pragma unroll
            for (int mi = 0; mi < 2; mi++) {
                uint32_t ad = aBase + AHI_O + (uint32_t)mi * 16 * ROWB + ks * 32 + laneA;
                ldsm4(ah[mi][0], ah[mi][1], ah[mi][2], ah[mi][3], ad);
                uint32_t ad2 = aBase + ALO_O + (uint32_t)mi * 16 * ROWB + ks * 32 + laneA;
                ldsm4(al[mi][0], al[mi][1], al[mi][2], al[mi][3], ad2);
            }
#pragma unroll
            for (int nj = 0; nj < 2; nj++) {
                uint32_t bd = bBase + BHI_O + (uint32_t)nj * 16 * ROWB + ks * 32 + laneB;
                ldsm4(bh[2 * nj][0], bh[2 * nj][1], bh[2 * nj + 1][0], bh[2 * nj + 1][1], bd);
                uint32_t bd2 = bBase + BLO_O + (uint32_t)nj * 16 * ROWB + ks * 32 + laneB;
                ldsm4(bl[2 * nj][0], bl[2 * nj][1], bl[2 * nj + 1][0], bl[2 * nj + 1][1], bd2);
            }
            // term-outer ordering: 8 independent MMAs between RAW-dependent pairs
#pragma unroll
            for (int mi = 0; mi < 2; mi++)
#pragma unroll
                for (int ni = 0; ni < 4; ni++)
                    mma16816(acc[mi][ni], ah[mi], bh[ni]);
#pragma unroll
            for (int mi = 0; mi < 2; mi++)
#pragma unroll
                for (int ni = 0; ni < 4; ni++)
                    mma16816(acc[mi][ni], ah[mi], bl[ni]);
#pragma unroll
            for (int mi = 0; mi < 2; mi++)
#pragma unroll
                for (int ni = 0; ni < 4; ni++)
                    mma16816(acc[mi][ni], al[mi], bh[ni]);
        }

        if (++slot == NSTAGE) slot = 0;
    }

    // epilogue: bias + store fp32
#pragma unroll
    for (int mi = 0; mi < 2; mi++) {
        int r0 = bm + wm * 32 + mi * 16 + (lane >> 2);
#pragma unroll
        for (int ni = 0; ni < 4; ni++) {
            int cix = bn + wn * 32 + ni * 8 + (lane & 3) * 2;
            float2 bv = *(const float2*)(bias + cix);
            float2 o0, o1;
            o0.x = acc[mi][ni][0] + bv.x; o0.y = acc[mi][ni][1] + bv.y;
            o1.x = acc[mi][ni][2] + bv.x; o1.y = acc[mi][ni][3] + bv.y;
            *(float2*)(C + (size_t)r0 * DIM + cix) = o0;
            *(float2*)(C + (size_t)(r0 + 8) * DIM + cix) = o1;
        }
    }
}

// ---------------- fp32 -> bf16 hi/lo split ----------------
__global__ __launch_bounds__(256) void split_bf16(
    const float4* __restrict__ in, __nv_bfloat162* __restrict__ hi,
    __nv_bfloat162* __restrict__ lo, int n4)
{
    int i = blockIdx.x * blockDim.x + threadIdx.x;
    if (i >= n4) return;
    float4 v = in[i];
    __nv_bfloat16 h0 = __float2bfloat16(v.x);
    __nv_bfloat16 h1 = __float2bfloat16(v.y);
    __nv_bfloat16 h2 = __float2bfloat16(v.z);
    __nv_bfloat16 h3 = __float2bfloat16(v.w);
    __nv_bfloat16 l0 = __float2bfloat16(v.x - __bfloat162float(h0));
    __nv_bfloat16 l1 = __float2bfloat16(v.y - __bfloat162float(h1));
    __nv_bfloat16 l2 = __float2bfloat16(v.z - __bfloat162float(h2));
    __nv_bfloat16 l3 = __float2bfloat16(v.w - __bfloat162float(h3));
    hi[2 * i + 0] = __nv_bfloat162(h0, h1);
    hi[2 * i + 1] = __nv_bfloat162(h2, h3);
    lo[2 * i + 0] = __nv_bfloat162(l0, l1);
    lo[2 * i + 1] = __nv_bfloat162(l2, l3);
}

// ---------------- scan (3-stage chunked linear recurrence) ----------------
__global__ __launch_bounds__(256) void scan_partial(
    const float* __restrict__ h, const float* __restrict__ a,
    const float* __restrict__ bgate, float* __restrict__ partial)
{
    const int d = blockIdx.x * blockDim.x + threadIdx.x;
    const int c = blockIdx.y;
    const int b = blockIdx.z;
    const float A  = 1.f / (1.f + expf(-a[d]));
    const float bb = bgate[d];
    const float* hp = h + ((size_t)(b * SEQ + c * CHUNK)) * DIM + d;
    float s = 0.f;
#pragma unroll 8
    for (int t = 0; t < CHUNK; t++)
        s = fmaf(A, s, bb * hp[(size_t)t * DIM]);
    partial[(b * NCHUNK + c) * DIM + d] = s;
}

__global__ __launch_bounds__(256) void scan_carries(
    const float* __restrict__ partial, const float* __restrict__ a,
    float* __restrict__ carry)
{
    const int d = blockIdx.x * blockDim.x + threadIdx.x;
    const int b = blockIdx.y;
    const float A = 1.f / (1.f + expf(-a[d]));
    float Ap = A;
#pragma unroll
    for (int i = 0; i < 8; i++) Ap *= Ap;   // A^256
    float s = 0.f;
#pragma unroll
    for (int c = 0; c < NCHUNK; c++) {
        s = fmaf(Ap, s, partial[(b * NCHUNK + c) * DIM + d]);
        carry[(b * NCHUNK + c) * DIM + d] = s;
    }
}

__global__ __launch_bounds__(256) void scan_apply(
    const float* __restrict__ h, const float* __restrict__ a,
    const float* __restrict__ bgate, const float* __restrict__ carry,
    __nv_bfloat16* __restrict__ yhi, __nv_bfloat16* __restrict__ ylo)
{
    const int d = blockIdx.x * blockDim.x + threadIdx.x;
    const int c = blockIdx.y;
    const int b = blockIdx.z;
    const float A  = 1.f / (1.f + expf(-a[d]));
    const float bb = bgate[d];

    float s = (c == 0) ? 0.f : carry[(b * NCHUNK + (c - 1)) * DIM + d];

    const size_t off = (size_t)(b * SEQ + c * CHUNK) * DIM + d;
    const float* hp = h + off;
#pragma unroll 8
    for (int t = 0; t < CHUNK; t++) {
        s = fmaf(A, s, bb * hp[(size_t)t * DIM]);
        __nv_bfloat16 hv = __float2bfloat16(s);
        yhi[off + (size_t)t * DIM] = hv;
        ylo[off + (size_t)t * DIM] = __float2bfloat16(s - __bfloat162float(hv));
    }
}

// ---------------------------------------------------------------------------
extern "C" void kernel_launch(void* const* d_in, const int* in_sizes, int n_in,
                              void* d_out, int out_size)
{
    const float* x     = (const float*)d_in[0];
    const float* w_in  = (const float*)d_in[1];
    const float* b_in  = (const float*)d_in[2];
    const float* a     = (const float*)d_in[3];
    const float* bg    = (const float*)d_in[4];
    const float* w_out = (const float*)d_in[5];
    const float* b_out = (const float*)d_in[6];
    float* out = (float*)d_out;

    float *h, *partial, *carry;
    __nv_bfloat16 *ahi, *alo, *wihi, *wilo, *wohi, *wolo;
    cudaGetSymbolAddress((void**)&h, g_h);
    cudaGetSymbolAddress((void**)&ahi, g_ahi);
    cudaGetSymbolAddress((void**)&alo, g_alo);
    cudaGetSymbolAddress((void**)&wihi, g_wihi);
    cudaGetSymbolAddress((void**)&wilo, g_wilo);
    cudaGetSymbolAddress((void**)&wohi, g_wohi);
    cudaGetSymbolAddress((void**)&wolo, g_wolo);
    cudaGetSymbolAddress((void**)&partial, g_partial);
    cudaGetSymbolAddress((void**)&carry, g_carry);

    cudaFuncSetAttribute(gemm_bf16x3, cudaFuncAttributeMaxDynamicSharedMemorySize, GEMM_SMEM);

    // split x and weights to bf16 hi/lo
    {
        int n4 = MTOT * DIM / 4;
        split_bf16<<<n4 / 256, 256>>>((const float4*)x, (__nv_bfloat162*)ahi,
                                      (__nv_bfloat162*)alo, n4);
        int w4 = DIM * DIM / 4;
        split_bf16<<<w4 / 256, 256>>>((const float4*)w_in, (__nv_bfloat162*)wihi,
                                      (__nv_bfloat162*)wilo, w4);
        split_bf16<<<w4 / 256, 256>>>((const float4*)w_out, (__nv_bfloat162*)wohi,
                                      (__nv_bfloat162*)wolo, w4);
    }

    // GEMM 1: h = x @ w_in^T + b_in
    {
        dim3 grid(DIM / GBN, MTOT / GBM);
        gemm_bf16x3<<<grid, NTHREADS, GEMM_SMEM>>>(ahi, alo, wihi, wilo, b_in, h);
    }

    // scan; scan_apply writes the bf16 split of y into ahi/alo
    {
        dim3 g1(DIM / 256, NCHUNK, BATCH);
        scan_partial<<<g1, 256>>>(h, a, bg, partial);
        dim3 g2(DIM / 256, BATCH);
        scan_carries<<<g2, 256>>>(partial, a, carry);
        dim3 g3(DIM / 256, NCHUNK, BATCH);
        scan_apply<<<g3, 256>>>(h, a, bg, carry, ahi, alo);
    }

    // GEMM 2: out = y @ w_out^T + b_out
    {
        dim3 grid(DIM / GBN, MTOT / GBM);
        gemm_bf16x3<<<grid, NTHREADS, GEMM_SMEM>>>(ahi, alo, wohi, wolo, b_out, out);
    }
}

// round 9
// speedup vs baseline: 7.9685x; 2.2592x over previous
#include <cuda_runtime.h>
#include <cuda_fp16.h>
#include <cstdint>
#include <math.h>

#define DIM    1024
#define BATCH  4
#define SEQ    8192
#define MTOT   (BATCH * SEQ)      // 32768
#define CHUNK  256
#define NCHUNK (SEQ / CHUNK)      // 32

// ---------------- scratch (device globals; no allocs allowed) ----------------
__device__ float  g_h[MTOT * DIM];          // in_proj output (fp32)
__device__ __half g_xf[MTOT * DIM];         // x as fp16, later y as fp16
__device__ __half g_wif[DIM * DIM];         // w_in fp16
__device__ __half g_wof[DIM * DIM];         // w_out fp16
__device__ float  g_partial[BATCH * NCHUNK * DIM];
__device__ float  g_carry[BATCH * NCHUNK * DIM];

// ---------------- PTX helpers (base ISA only) ----------
__device__ __forceinline__ uint32_t smem_u32(const void* p) {
    uint32_t a;
    asm("{ .reg .u64 t; cvta.to.shared.u64 t, %1; cvt.u32.u64 %0, t; }" : "=r"(a) : "l"(p));
    return a;
}
__device__ __forceinline__ void cp16(uint32_t saddr, const void* gaddr) {
    asm volatile("cp.async.cg.shared.global [%0], [%1], 16;" :: "r"(saddr), "l"(gaddr) : "memory");
}
__device__ __forceinline__ void ldsm4(uint32_t& r0, uint32_t& r1, uint32_t& r2, uint32_t& r3,
                                      uint32_t addr) {
    asm volatile("ldmatrix.sync.aligned.m8n8.x4.shared.b16 {%0,%1,%2,%3}, [%4];"
                 : "=r"(r0), "=r"(r1), "=r"(r2), "=r"(r3) : "r"(addr));
}
__device__ __forceinline__ void mma16816(float* d, const uint32_t* a, const uint32_t* b) {
    asm volatile(
        "mma.sync.aligned.m16n8k16.row.col.f32.f16.f16.f32 "
        "{%0,%1,%2,%3}, {%4,%5,%6,%7}, {%8,%9}, {%0,%1,%2,%3};"
        : "+f"(d[0]), "+f"(d[1]), "+f"(d[2]), "+f"(d[3])
        : "r"(a[0]), "r"(a[1]), "r"(a[2]), "r"(a[3]), "r"(b[0]), "r"(b[1]));
}

// ---------------- GEMM: C[m,n] = A[m,:]·B[n,:] + bias[n]   (fp16 in, fp32 out)
// CTA tile 128x256, BK=32, 8 warps (64x64 each), 4-stage cp.async pipeline,
// one syncthreads per k-iter. Smem rows padded to 80B (conflict-free ldmatrix).
// ----------------------------------------------------------------------------
#define GBM 128
#define GBN 256
#define GBK 32
#define KITERS (DIM / GBK)          // 32
#define ROWB   80                   // 32 fp16 = 64B + 16B pad
#define A_O    0
#define B_O    (GBM * ROWB)                     // 10240
#define STAGE_B ((GBM + GBN) * ROWB)            // 30720
#define NSTAGE 4
#define GEMM_SMEM (NSTAGE * STAGE_B)            // 122880
#define NTHREADS 256

__device__ __forceinline__ void load_stage(
    uint32_t sstage, const char* pA, const char* pB, int kbyte, int tid)
{
    // A: 128 rows x 4 x 16B chunks = 512 chunks
#pragma unroll
    for (int j = 0; j < 2; j++) {
        int id = tid + j * NTHREADS;            // 0..511
        int row = id >> 2, c = id & 3;
        cp16(sstage + A_O + row * ROWB + c * 16,
             pA + (size_t)row * 2048 + kbyte + c * 16);
    }
    // B: 256 rows x 4 chunks = 1024 chunks
#pragma unroll
    for (int j = 0; j < 4; j++) {
        int id = tid + j * NTHREADS;            // 0..1023
        int row = id >> 2, c = id & 3;
        cp16(sstage + B_O + row * ROWB + c * 16,
             pB + (size_t)row * 2048 + kbyte + c * 16);
    }
}

__global__ __launch_bounds__(NTHREADS, 1)
void gemm_fp16(const __half* __restrict__ A, const __half* __restrict__ B,
               const float* __restrict__ bias, float* __restrict__ C)
{
    extern __shared__ char smem[];
    const uint32_t sbase = smem_u32(smem);
    const int tid = threadIdx.x, wid = tid >> 5, lane = tid & 31;
    const int bn = blockIdx.x * GBN;
    const int bm = blockIdx.y * GBM;
    const int wm = wid & 1;            // 0..1 -> 64-row slab
    const int wn = wid >> 1;           // 0..3 -> 64-col slab

    const char* pA = (const char*)A + (size_t)bm * 2048;
    const char* pB = (const char*)B + (size_t)bn * 2048;

    float acc[4][8][4];
#pragma unroll
    for (int i = 0; i < 4; i++)
#pragma unroll
        for (int j = 0; j < 8; j++)
#pragma unroll
            for (int r = 0; r < 4; r++) acc[i][j][r] = 0.f;

    const uint32_t laneA = (uint32_t)(lane & 15) * ROWB + (uint32_t)(lane >> 4) * 16;
    const uint32_t laneB = (uint32_t)((lane & 7) + ((lane >> 4) << 3)) * ROWB
                         + (uint32_t)((lane >> 3) & 1) * 16;

    // prologue: stages 0,1,2
    load_stage(sbase + 0 * STAGE_B, pA, pB, 0, tid);
    asm volatile("cp.async.commit_group;" ::: "memory");
    load_stage(sbase + 1 * STAGE_B, pA, pB, GBK * 2, tid);
    asm volatile("cp.async.commit_group;" ::: "memory");
    load_stage(sbase + 2 * STAGE_B, pA, pB, 2 * GBK * 2, tid);
    asm volatile("cp.async.commit_group;" ::: "memory");

    for (int i = 0; i < KITERS; i++) {
        if (i < KITERS - 2)
            asm volatile("cp.async.wait_group 2;" ::: "memory");
        else if (i == KITERS - 2)
            asm volatile("cp.async.wait_group 1;" ::: "memory");
        else
            asm volatile("cp.async.wait_group 0;" ::: "memory");
        __syncthreads();

        if (i + 3 < KITERS) {
            load_stage(sbase + ((i + 3) & 3) * STAGE_B, pA, pB, (i + 3) * (GBK * 2), tid);
            asm volatile("cp.async.commit_group;" ::: "memory");
        }

        const uint32_t sg = sbase + (i & 3) * STAGE_B;
        const uint32_t aBase = sg + A_O + (uint32_t)wm * 64 * ROWB;
        const uint32_t bBase = sg + B_O + (uint32_t)wn * 64 * ROWB;

#pragma unroll
        for (int ks = 0; ks < 2; ks++) {
            uint32_t af[4][4];
#pragma unroll
            for (int mi = 0; mi < 4; mi++)
                ldsm4(af[mi][0], af[mi][1], af[mi][2], af[mi][3],
                      aBase + (uint32_t)mi * 16 * ROWB + ks * 32 + laneA);
#pragma unroll
            for (int nh = 0; nh < 4; nh++) {
                uint32_t b0[2], b1[2];
                ldsm4(b0[0], b0[1], b1[0], b1[1],
                      bBase + (uint32_t)nh * 16 * ROWB + ks * 32 + laneB);
#pragma unroll
                for (int mi = 0; mi < 4; mi++) {
                    mma16816(acc[mi][2 * nh],     af[mi], b0);
                    mma16816(acc[mi][2 * nh + 1], af[mi], b1);
                }
            }
        }
    }

    // epilogue: bias + store fp32
#pragma unroll
    for (int mi = 0; mi < 4; mi++) {
        int r0 = bm + wm * 64 + mi * 16 + (lane >> 2);
#pragma unroll
        for (int ni = 0; ni < 8; ni++) {
            int cix = bn + wn * 64 + ni * 8 + (lane & 3) * 2;
            float2 bv = *(const float2*)(bias + cix);
            float2 o0, o1;
            o0.x = acc[mi][ni][0] + bv.x; o0.y = acc[mi][ni][1] + bv.y;
            o1.x = acc[mi][ni][2] + bv.x; o1.y = acc[mi][ni][3] + bv.y;
            *(float2*)(C + (size_t)r0 * DIM + cix) = o0;
            *(float2*)(C + (size_t)(r0 + 8) * DIM + cix) = o1;
        }
    }
}

// ---------------- fp32 -> fp16 convert ----------------
__global__ __launch_bounds__(256) void to_fp16(
    const float4* __restrict__ in, __half2* __restrict__ out, int n4)
{
    int i = blockIdx.x * blockDim.x + threadIdx.x;
    if (i >= n4) return;
    float4 v = in[i];
    out[2 * i + 0] = __floats2half2_rn(v.x, v.y);
    out[2 * i + 1] = __floats2half2_rn(v.z, v.w);
}

// ---------------- scan (3-stage chunked linear recurrence) ----------------
__global__ __launch_bounds__(256) void scan_partial(
    const float* __restrict__ h, const float* __restrict__ a,
    const float* __restrict__ bgate, float* __restrict__ partial)
{
    const int d = blockIdx.x * blockDim.x + threadIdx.x;
    const int c = blockIdx.y;
    const int b = blockIdx.z;
    const float A  = 1.f / (1.f + expf(-a[d]));
    const float bb = bgate[d];
    const float* hp = h + ((size_t)(b * SEQ + c * CHUNK)) * DIM + d;
    float s = 0.f;
#pragma unroll 8
    for (int t = 0; t < CHUNK; t++)
        s = fmaf(A, s, bb * hp[(size_t)t * DIM]);
    partial[(b * NCHUNK + c) * DIM + d] = s;
}

__global__ __launch_bounds__(256) void scan_carries(
    const float* __restrict__ partial, const float* __restrict__ a,
    float* __restrict__ carry)
{
    const int d = blockIdx.x * blockDim.x + threadIdx.x;
    const int b = blockIdx.y;
    const float A = 1.f / (1.f + expf(-a[d]));
    float Ap = A;
#pragma unroll
    for (int i = 0; i < 8; i++) Ap *= Ap;   // A^256
    float s = 0.f;
#pragma unroll
    for (int c = 0; c < NCHUNK; c++) {
        s = fmaf(Ap, s, partial[(b * NCHUNK + c) * DIM + d]);
        carry[(b * NCHUNK + c) * DIM + d] = s;
    }
}

// replay each chunk from the correct carry; emit y as fp16
__global__ __launch_bounds__(256) void scan_apply(
    const float* __restrict__ h, const float* __restrict__ a,
    const float* __restrict__ bgate, const float* __restrict__ carry,
    __half* __restrict__ yf)
{
    const int d = blockIdx.x * blockDim.x + threadIdx.x;
    const int c = blockIdx.y;
    const int b = blockIdx.z;
    const float A  = 1.f / (1.f + expf(-a[d]));
    const float bb = bgate[d];

    float s = (c == 0) ? 0.f : carry[(b * NCHUNK + (c - 1)) * DIM + d];

    const size_t off = (size_t)(b * SEQ + c * CHUNK) * DIM + d;
    const float* hp = h + off;
#pragma unroll 8
    for (int t = 0; t < CHUNK; t++) {
        s = fmaf(A, s, bb * hp[(size_t)t * DIM]);
        yf[off + (size_t)t * DIM] = __float2half_rn(s);
    }
}

// ---------------------------------------------------------------------------
extern "C" void kernel_launch(void* const* d_in, const int* in_sizes, int n_in,
                              void* d_out, int out_size)
{
    const float* x     = (const float*)d_in[0];
    const float* w_in  = (const float*)d_in[1];
    const float* b_in  = (const float*)d_in[2];
    const float* a     = (const float*)d_in[3];
    const float* bg    = (const float*)d_in[4];
    const float* w_out = (const float*)d_in[5];
    const float* b_out = (const float*)d_in[6];
    float* out = (float*)d_out;

    float *h, *partial, *carry;
    __half *xf, *wif, *wof;
    cudaGetSymbolAddress((void**)&h, g_h);
    cudaGetSymbolAddress((void**)&xf, g_xf);
    cudaGetSymbolAddress((void**)&wif, g_wif);
    cudaGetSymbolAddress((void**)&wof, g_wof);
    cudaGetSymbolAddress((void**)&partial, g_partial);
    cudaGetSymbolAddress((void**)&carry, g_carry);

    cudaFuncSetAttribute(gemm_fp16, cudaFuncAttributeMaxDynamicSharedMemorySize, GEMM_SMEM);

    // convert inputs to fp16
    {
        int n4 = MTOT * DIM / 4;
        to_fp16<<<n4 / 256, 256>>>((const float4*)x, (__half2*)xf, n4);
        int w4 = DIM * DIM / 4;
        to_fp16<<<w4 / 256, 256>>>((const float4*)w_in, (__half2*)wif, w4);
        to_fp16<<<w4 / 256, 256>>>((const float4*)w_out, (__half2*)wof, w4);
    }

    // GEMM 1: h = x @ w_in^T + b_in
    {
        dim3 grid(DIM / GBN, MTOT / GBM);
        gemm_fp16<<<grid, NTHREADS, GEMM_SMEM>>>(xf, wif, b_in, h);
    }

    // scan; scan_apply writes fp16 y into xf (reuse)
    {
        dim3 g1(DIM / 256, NCHUNK, BATCH);
        scan_partial<<<g1, 256>>>(h, a, bg, partial);
        dim3 g2(DIM / 256, BATCH);
        scan_carries<<<g2, 256>>>(partial, a, carry);
        dim3 g3(DIM / 256, NCHUNK, BATCH);
        scan_apply<<<g3, 256>>>(h, a, bg, carry, xf);
    }

    // GEMM 2: out = y @ w_out^T + b_out
    {
        dim3 grid(DIM / GBN, MTOT / GBM);
        gemm_fp16<<<grid, NTHREADS, GEMM_SMEM>>>(xf, wof, b_out, out);
    }
}

// round 11
// speedup vs baseline: 8.2185x; 1.0314x over previous
#include <cuda_runtime.h>
#include <cuda_fp16.h>
#include <cstdint>
#include <math.h>

#define DIM    1024
#define BATCH  4
#define SEQ    8192
#define MTOT   (BATCH * SEQ)      // 32768
#define CHUNK  256
#define NCHUNK (SEQ / CHUNK)      // 32

// ---------------- scratch (device globals; no allocs allowed) ----------------
__device__ float  g_h[MTOT * DIM];          // in_proj output (fp32)
__device__ __half g_xf[MTOT * DIM];         // x as fp16, later y as fp16
__device__ __half g_wif[DIM * DIM];         // w_in fp16
__device__ __half g_wof[DIM * DIM];         // w_out fp16
__device__ float  g_partial[BATCH * NCHUNK * DIM];
__device__ float  g_carry[BATCH * NCHUNK * DIM];

// ---------------- PTX helpers (base ISA only) ----------
__device__ __forceinline__ uint32_t smem_u32(const void* p) {
    uint32_t a;
    asm("{ .reg .u64 t; cvta.to.shared.u64 t, %1; cvt.u32.u64 %0, t; }" : "=r"(a) : "l"(p));
    return a;
}
__device__ __forceinline__ void cp16(uint32_t saddr, const void* gaddr) {
    asm volatile("cp.async.cg.shared.global [%0], [%1], 16;" :: "r"(saddr), "l"(gaddr) : "memory");
}
__device__ __forceinline__ void ldsm4(uint32_t& r0, uint32_t& r1, uint32_t& r2, uint32_t& r3,
                                      uint32_t addr) {
    asm volatile("ldmatrix.sync.aligned.m8n8.x4.shared.b16 {%0,%1,%2,%3}, [%4];"
                 : "=r"(r0), "=r"(r1), "=r"(r2), "=r"(r3) : "r"(addr));
}
__device__ __forceinline__ void mma16816(float* d, const uint32_t* a, const uint32_t* b) {
    asm volatile(
        "mma.sync.aligned.m16n8k16.row.col.f32.f16.f16.f32 "
        "{%0,%1,%2,%3}, {%4,%5,%6,%7}, {%8,%9}, {%0,%1,%2,%3};"
        : "+f"(d[0]), "+f"(d[1]), "+f"(d[2]), "+f"(d[3])
        : "r"(a[0]), "r"(a[1]), "r"(a[2]), "r"(a[3]), "r"(b[0]), "r"(b[1]));
}

// ---------------- GEMM: C[m,n] = A[m,:]·B[n,:] + bias[n]   (fp16 in, fp32 out)
// CTA tile 128x256, BK=32, 512 threads / 16 warps (32x64 each), 4-stage
// cp.async pipeline, one syncthreads per k-iter. Smem rows padded to 80B.
// ----------------------------------------------------------------------------
#define GBM 128
#define GBN 256
#define GBK 32
#define KITERS (DIM / GBK)          // 32
#define ROWB   80                   // 32 fp16 = 64B + 16B pad
#define A_O    0
#define B_O    (GBM * ROWB)                     // 10240
#define STAGE_B ((GBM + GBN) * ROWB)            // 30720
#define NSTAGE 4
#define GEMM_SMEM (NSTAGE * STAGE_B)            // 122880
#define NTHREADS 512

__device__ __forceinline__ void load_stage(
    uint32_t sstage, const char* pA, const char* pB, int kbyte, int tid)
{
    // A: 128 rows x 4 x 16B chunks = 512 chunks (one per thread)
    {
        int row = tid >> 2, c = tid & 3;
        cp16(sstage + A_O + row * ROWB + c * 16,
             pA + (size_t)row * 2048 + kbyte + c * 16);
    }
    // B: 256 rows x 4 chunks = 1024 chunks (two per thread)
#pragma unroll
    for (int j = 0; j < 2; j++) {
        int id = tid + j * NTHREADS;            // 0..1023
        int row = id >> 2, c = id & 3;
        cp16(sstage + B_O + row * ROWB + c * 16,
             pB + (size_t)row * 2048 + kbyte + c * 16);
    }
}

__global__ __launch_bounds__(NTHREADS, 1)
void gemm_fp16(const __half* __restrict__ A, const __half* __restrict__ B,
               const float* __restrict__ bias, float* __restrict__ C)
{
    extern __shared__ char smem[];
    const uint32_t sbase = smem_u32(smem);
    const int tid = threadIdx.x, wid = tid >> 5, lane = tid & 31;
    const int bn = blockIdx.x * GBN;
    const int bm = blockIdx.y * GBM;
    const int wm = wid & 3;            // 0..3 -> 32-row slab
    const int wn = wid >> 2;           // 0..3 -> 64-col slab

    const char* pA = (const char*)A + (size_t)bm * 2048;
    const char* pB = (const char*)B + (size_t)bn * 2048;

    float acc[2][8][4];
#pragma unroll
    for (int i = 0; i < 2; i++)
#pragma unroll
        for (int j = 0; j < 8; j++)
#pragma unroll
            for (int r = 0; r < 4; r++) acc[i][j][r] = 0.f;

    const uint32_t laneA = (uint32_t)(lane & 15) * ROWB + (uint32_t)(lane >> 4) * 16;
    const uint32_t laneB = (uint32_t)((lane & 7) + ((lane >> 4) << 3)) * ROWB
                         + (uint32_t)((lane >> 3) & 1) * 16;

    // prologue: stages 0,1,2
    load_stage(sbase + 0 * STAGE_B, pA, pB, 0, tid);
    asm volatile("cp.async.commit_group;" ::: "memory");
    load_stage(sbase + 1 * STAGE_B, pA, pB, GBK * 2, tid);
    asm volatile("cp.async.commit_group;" ::: "memory");
    load_stage(sbase + 2 * STAGE_B, pA, pB, 2 * GBK * 2, tid);
    asm volatile("cp.async.commit_group;" ::: "memory");

    for (int i = 0; i < KITERS; i++) {
        if (i < KITERS - 2)
            asm volatile("cp.async.wait_group 2;" ::: "memory");
        else if (i == KITERS - 2)
            asm volatile("cp.async.wait_group 1;" ::: "memory");
        else
            asm volatile("cp.async.wait_group 0;" ::: "memory");
        __syncthreads();

        if (i + 3 < KITERS) {
            load_stage(sbase + ((i + 3) & 3) * STAGE_B, pA, pB, (i + 3) * (GBK * 2), tid);
            asm volatile("cp.async.commit_group;" ::: "memory");
        }

        const uint32_t sg = sbase + (i & 3) * STAGE_B;
        const uint32_t aBase = sg + A_O + (uint32_t)wm * 32 * ROWB;
        const uint32_t bBase = sg + B_O + (uint32_t)wn * 64 * ROWB;

#pragma unroll
        for (int ks = 0; ks < 2; ks++) {
            uint32_t af[2][4];
#pragma unroll
            for (int mi = 0; mi < 2; mi++)
                ldsm4(af[mi][0], af[mi][1], af[mi][2], af[mi][3],
                      aBase + (uint32_t)mi * 16 * ROWB + ks * 32 + laneA);
#pragma unroll
            for (int nh = 0; nh < 4; nh++) {
                uint32_t b0[2], b1[2];
                ldsm4(b0[0], b0[1], b1[0], b1[1],
                      bBase + (uint32_t)nh * 16 * ROWB + ks * 32 + laneB);
#pragma unroll
                for (int mi = 0; mi < 2; mi++) {
                    mma16816(acc[mi][2 * nh],     af[mi], b0);
                    mma16816(acc[mi][2 * nh + 1], af[mi], b1);
                }
            }
        }
    }

    // epilogue: bias + store fp32
#pragma unroll
    for (int mi = 0; mi < 2; mi++) {
        int r0 = bm + wm * 32 + mi * 16 + (lane >> 2);
#pragma unroll
        for (int ni = 0; ni < 8; ni++) {
            int cix = bn + wn * 64 + ni * 8 + (lane & 3) * 2;
            float2 bv = *(const float2*)(bias + cix);
            float2 o0, o1;
            o0.x = acc[mi][ni][0] + bv.x; o0.y = acc[mi][ni][1] + bv.y;
            o1.x = acc[mi][ni][2] + bv.x; o1.y = acc[mi][ni][3] + bv.y;
            *(float2*)(C + (size_t)r0 * DIM + cix) = o0;
            *(float2*)(C + (size_t)(r0 + 8) * DIM + cix) = o1;
        }
    }
}

// ---------------- fp32 -> fp16 convert ----------------
__global__ __launch_bounds__(256) void to_fp16(
    const float4* __restrict__ in, __half2* __restrict__ out, int n4)
{
    int i = blockIdx.x * blockDim.x + threadIdx.x;
    if (i >= n4) return;
    float4 v = in[i];
    out[2 * i + 0] = __floats2half2_rn(v.x, v.y);
    out[2 * i + 1] = __floats2half2_rn(v.z, v.w);
}

// ---------------- scan (3-stage chunked linear recurrence) ----------------
__global__ __launch_bounds__(256) void scan_partial(
    const float* __restrict__ h, const float* __restrict__ a,
    const float* __restrict__ bgate, float* __restrict__ partial)
{
    const int d = blockIdx.x * blockDim.x + threadIdx.x;
    const int c = blockIdx.y;
    const int b = blockIdx.z;
    const float A  = 1.f / (1.f + expf(-a[d]));
    const float bb = bgate[d];
    const float* hp = h + ((size_t)(b * SEQ + c * CHUNK)) * DIM + d;
    float s = 0.f;
#pragma unroll 8
    for (int t = 0; t < CHUNK; t++)
        s = fmaf(A, s, bb * hp[(size_t)t * DIM]);
    partial[(b * NCHUNK + c) * DIM + d] = s;
}

__global__ __launch_bounds__(256) void scan_carries(
    const float* __restrict__ partial, const float* __restrict__ a,
    float* __restrict__ carry)
{
    const int d = blockIdx.x * blockDim.x + threadIdx.x;
    const int b = blockIdx.y;
    const float A = 1.f / (1.f + expf(-a[d]));
    float Ap = A;
#pragma unroll
    for (int i = 0; i < 8; i++) Ap *= Ap;   // A^256
    float s = 0.f;
#pragma unroll
    for (int c = 0; c < NCHUNK; c++) {
        s = fmaf(Ap, s, partial[(b * NCHUNK + c) * DIM + d]);
        carry[(b * NCHUNK + c) * DIM + d] = s;
    }
}

// replay each chunk from the correct carry; emit y as fp16
__global__ __launch_bounds__(256) void scan_apply(
    const float* __restrict__ h, const float* __restrict__ a,
    const float* __restrict__ bgate, const float* __restrict__ carry,
    __half* __restrict__ yf)
{
    const int d = blockIdx.x * blockDim.x + threadIdx.x;
    const int c = blockIdx.y;
    const int b = blockIdx.z;
    const float A  = 1.f / (1.f + expf(-a[d]));
    const float bb = bgate[d];

    float s = (c == 0) ? 0.f : carry[(b * NCHUNK + (c - 1)) * DIM + d];

    const size_t off = (size_t)(b * SEQ + c * CHUNK) * DIM + d;
    const float* hp = h + off;
#pragma unroll 8
    for (int t = 0; t < CHUNK; t++) {
        s = fmaf(A, s, bb * hp[(size_t)t * DIM]);
        yf[off + (size_t)t * DIM] = __float2half_rn(s);
    }
}

// ---------------------------------------------------------------------------
extern "C" void kernel_launch(void* const* d_in, const int* in_sizes, int n_in,
                              void* d_out, int out_size)
{
    const float* x     = (const float*)d_in[0];
    const float* w_in  = (const float*)d_in[1];
    const float* b_in  = (const float*)d_in[2];
    const float* a     = (const float*)d_in[3];
    const float* bg    = (const float*)d_in[4];
    const float* w_out = (const float*)d_in[5];
    const float* b_out = (const float*)d_in[6];
    float* out = (float*)d_out;

    float *h, *partial, *carry;
    __half *xf, *wif, *wof;
    cudaGetSymbolAddress((void**)&h, g_h);
    cudaGetSymbolAddress((void**)&xf, g_xf);
    cudaGetSymbolAddress((void**)&wif, g_wif);
    cudaGetSymbolAddress((void**)&wof, g_wof);
    cudaGetSymbolAddress((void**)&partial, g_partial);
    cudaGetSymbolAddress((void**)&carry, g_carry);

    cudaFuncSetAttribute(gemm_fp16, cudaFuncAttributeMaxDynamicSharedMemorySize, GEMM_SMEM);

    // convert inputs to fp16
    {
        int n4 = MTOT * DIM / 4;
        to_fp16<<<n4 / 256, 256>>>((const float4*)x, (__half2*)xf, n4);
        int w4 = DIM * DIM / 4;
        to_fp16<<<w4 / 256, 256>>>((const float4*)w_in, (__half2*)wif, w4);
        to_fp16<<<w4 / 256, 256>>>((const float4*)w_out, (__half2*)wof, w4);
    }

    // GEMM 1: h = x @ w_in^T + b_in
    {
        dim3 grid(DIM / GBN, MTOT / GBM);
        gemm_fp16<<<grid, NTHREADS, GEMM_SMEM>>>(xf, wif, b_in, h);
    }

    // scan; scan_apply writes fp16 y into xf (reuse)
    {
        dim3 g1(DIM / 256, NCHUNK, BATCH);
        scan_partial<<<g1, 256>>>(h, a, bg, partial);
        dim3 g2(DIM / 256, BATCH);
        scan_carries<<<g2, 256>>>(partial, a, carry);
        dim3 g3(DIM / 256, NCHUNK, BATCH);
        scan_apply<<<g3, 256>>>(h, a, bg, carry, xf);
    }

    // GEMM 2: out = y @ w_out^T + b_out
    {
        dim3 grid(DIM / GBN, MTOT / GBM);
        gemm_fp16<<<grid, NTHREADS, GEMM_SMEM>>>(xf, wof, b_out, out);
    }
}

// round 12
// speedup vs baseline: 8.8417x; 1.0758x over previous
#include <cuda_runtime.h>
#include <cuda_fp16.h>
#include <cstdint>
#include <math.h>

#define DIM    1024
#define BATCH  4
#define SEQ    8192
#define MTOT   (BATCH * SEQ)      // 32768
#define CHUNK  256
#define NCHUNK (SEQ / CHUNK)      // 32

// ---------------- scratch (device globals; no allocs allowed) ----------------
__device__ float  g_h[MTOT * DIM];          // in_proj output (fp32)
__device__ __half g_xf[MTOT * DIM];         // x as fp16, later y as fp16
__device__ __half g_wif[DIM * DIM];         // w_in fp16
__device__ __half g_wof[DIM * DIM];         // w_out fp16
__device__ float  g_partial[BATCH * NCHUNK * DIM];
__device__ float  g_carry[BATCH * NCHUNK * DIM];

// ---------------- PTX helpers (base ISA only) ----------
__device__ __forceinline__ uint32_t smem_u32(const void* p) {
    uint32_t a;
    asm("{ .reg .u64 t; cvta.to.shared.u64 t, %1; cvt.u32.u64 %0, t; }" : "=r"(a) : "l"(p));
    return a;
}
__device__ __forceinline__ void cp16(uint32_t saddr, const void* gaddr) {
    asm volatile("cp.async.cg.shared.global [%0], [%1], 16;" :: "r"(saddr), "l"(gaddr) : "memory");
}
__device__ __forceinline__ void ldsm4(uint32_t& r0, uint32_t& r1, uint32_t& r2, uint32_t& r3,
                                      uint32_t addr) {
    asm volatile("ldmatrix.sync.aligned.m8n8.x4.shared.b16 {%0,%1,%2,%3}, [%4];"
                 : "=r"(r0), "=r"(r1), "=r"(r2), "=r"(r3) : "r"(addr));
}
__device__ __forceinline__ void mma16816(float* d, const uint32_t* a, const uint32_t* b) {
    asm volatile(
        "mma.sync.aligned.m16n8k16.row.col.f32.f16.f16.f32 "
        "{%0,%1,%2,%3}, {%4,%5,%6,%7}, {%8,%9}, {%0,%1,%2,%3};"
        : "+f"(d[0]), "+f"(d[1]), "+f"(d[2]), "+f"(d[3])
        : "r"(a[0]), "r"(a[1]), "r"(a[2]), "r"(a[3]), "r"(b[0]), "r"(b[1]));
}

// ---------------- GEMM: C[m,n] = A[m,:]·B[n,:] + bias[n]   (fp16 in, fp32 out)
// CTA tile 128x128, BK=32, 256 threads / 8 warps (32x64 each), 4-stage
// cp.async pipeline, 2 CTAs per SM (anti-phased barriers). 80B-padded rows.
// ----------------------------------------------------------------------------
#define GBM 128
#define GBN 128
#define GBK 32
#define KITERS (DIM / GBK)          // 32
#define ROWB   80                   // 32 fp16 = 64B + 16B pad
#define A_O    0
#define B_O    (GBM * ROWB)                     // 10240
#define STAGE_B ((GBM + GBN) * ROWB)            // 20480
#define NSTAGE 4
#define GEMM_SMEM (NSTAGE * STAGE_B)            // 81920
#define NTHREADS 256

__device__ __forceinline__ void load_stage(
    uint32_t sstage, const char* pA, const char* pB, int kbyte, int tid)
{
    // A: 128 rows x 4 x 16B chunks = 512 chunks (two per thread)
#pragma unroll
    for (int j = 0; j < 2; j++) {
        int id = tid + j * NTHREADS;
        int row = id >> 2, c = id & 3;
        cp16(sstage + A_O + row * ROWB + c * 16,
             pA + (size_t)row * 2048 + kbyte + c * 16);
    }
    // B: 128 rows x 4 chunks = 512 chunks (two per thread)
#pragma unroll
    for (int j = 0; j < 2; j++) {
        int id = tid + j * NTHREADS;
        int row = id >> 2, c = id & 3;
        cp16(sstage + B_O + row * ROWB + c * 16,
             pB + (size_t)row * 2048 + kbyte + c * 16);
    }
}

__global__ __launch_bounds__(NTHREADS, 2)
void gemm_fp16(const __half* __restrict__ A, const __half* __restrict__ B,
               const float* __restrict__ bias, float* __restrict__ C)
{
    extern __shared__ char smem[];
    const uint32_t sbase = smem_u32(smem);
    const int tid = threadIdx.x, wid = tid >> 5, lane = tid & 31;
    const int bn = blockIdx.x * GBN;
    const int bm = blockIdx.y * GBM;
    const int wm = wid & 3;            // 0..3 -> 32-row slab
    const int wn = wid >> 2;           // 0..1 -> 64-col slab

    const char* pA = (const char*)A + (size_t)bm * 2048;
    const char* pB = (const char*)B + (size_t)bn * 2048;

    float acc[2][8][4];
#pragma unroll
    for (int i = 0; i < 2; i++)
#pragma unroll
        for (int j = 0; j < 8; j++)
#pragma unroll
            for (int r = 0; r < 4; r++) acc[i][j][r] = 0.f;

    const uint32_t laneA = (uint32_t)(lane & 15) * ROWB + (uint32_t)(lane >> 4) * 16;
    const uint32_t laneB = (uint32_t)((lane & 7) + ((lane >> 4) << 3)) * ROWB
                         + (uint32_t)((lane >> 3) & 1) * 16;

    // prologue: stages 0,1,2
    load_stage(sbase + 0 * STAGE_B, pA, pB, 0, tid);
    asm volatile("cp.async.commit_group;" ::: "memory");
    load_stage(sbase + 1 * STAGE_B, pA, pB, GBK * 2, tid);
    asm volatile("cp.async.commit_group;" ::: "memory");
    load_stage(sbase + 2 * STAGE_B, pA, pB, 2 * GBK * 2, tid);
    asm volatile("cp.async.commit_group;" ::: "memory");

    for (int i = 0; i < KITERS; i++) {
        if (i < KITERS - 2)
            asm volatile("cp.async.wait_group 2;" ::: "memory");
        else if (i == KITERS - 2)
            asm volatile("cp.async.wait_group 1;" ::: "memory");
        else
            asm volatile("cp.async.wait_group 0;" ::: "memory");
        __syncthreads();

        if (i + 3 < KITERS) {
            load_stage(sbase + ((i + 3) & 3) * STAGE_B, pA, pB, (i + 3) * (GBK * 2), tid);
            asm volatile("cp.async.commit_group;" ::: "memory");
        }

        const uint32_t sg = sbase + (i & 3) * STAGE_B;
        const uint32_t aBase = sg + A_O + (uint32_t)wm * 32 * ROWB;
        const uint32_t bBase = sg + B_O + (uint32_t)wn * 64 * ROWB;

#pragma unroll
        for (int ks = 0; ks < 2; ks++) {
            uint32_t af[2][4];
#pragma unroll
            for (int mi = 0; mi < 2; mi++)
                ldsm4(af[mi][0], af[mi][1], af[mi][2], af[mi][3],
                      aBase + (uint32_t)mi * 16 * ROWB + ks * 32 + laneA);
#pragma unroll
            for (int nh = 0; nh < 4; nh++) {
                uint32_t b0[2], b1[2];
                ldsm4(b0[0], b0[1], b1[0], b1[1],
                      bBase + (uint32_t)nh * 16 * ROWB + ks * 32 + laneB);
#pragma unroll
                for (int mi = 0; mi < 2; mi++) {
                    mma16816(acc[mi][2 * nh],     af[mi], b0);
                    mma16816(acc[mi][2 * nh + 1], af[mi], b1);
                }
            }
        }
    }

    // epilogue: bias + store fp32
#pragma unroll
    for (int mi = 0; mi < 2; mi++) {
        int r0 = bm + wm * 32 + mi * 16 + (lane >> 2);
#pragma unroll
        for (int ni = 0; ni < 8; ni++) {
            int cix = bn + wn * 64 + ni * 8 + (lane & 3) * 2;
            float2 bv = *(const float2*)(bias + cix);
            float2 o0, o1;
            o0.x = acc[mi][ni][0] + bv.x; o0.y = acc[mi][ni][1] + bv.y;
            o1.x = acc[mi][ni][2] + bv.x; o1.y = acc[mi][ni][3] + bv.y;
            *(float2*)(C + (size_t)r0 * DIM + cix) = o0;
            *(float2*)(C + (size_t)(r0 + 8) * DIM + cix) = o1;
        }
    }
}

// ---------------- fp32 -> fp16 convert ----------------
__global__ __launch_bounds__(256) void to_fp16(
    const float4* __restrict__ in, __half2* __restrict__ out, int n4)
{
    int i = blockIdx.x * blockDim.x + threadIdx.x;
    if (i >= n4) return;
    float4 v = in[i];
    out[2 * i + 0] = __floats2half2_rn(v.x, v.y);
    out[2 * i + 1] = __floats2half2_rn(v.z, v.w);
}

// ---------------- scan (3-stage chunked linear recurrence) ----------------
__global__ __launch_bounds__(256) void scan_partial(
    const float* __restrict__ h, const float* __restrict__ a,
    const float* __restrict__ bgate, float* __restrict__ partial)
{
    const int d = blockIdx.x * blockDim.x + threadIdx.x;
    const int c = blockIdx.y;
    const int b = blockIdx.z;
    const float A  = 1.f / (1.f + expf(-a[d]));
    const float bb = bgate[d];
    const float* hp = h + ((size_t)(b * SEQ + c * CHUNK)) * DIM + d;
    float s = 0.f;
#pragma unroll 8
    for (int t = 0; t < CHUNK; t++)
        s = fmaf(A, s, bb * hp[(size_t)t * DIM]);
    partial[(b * NCHUNK + c) * DIM + d] = s;
}

__global__ __launch_bounds__(256) void scan_carries(
    const float* __restrict__ partial, const float* __restrict__ a,
    float* __restrict__ carry)
{
    const int d = blockIdx.x * blockDim.x + threadIdx.x;
    const int b = blockIdx.y;
    const float A = 1.f / (1.f + expf(-a[d]));
    float Ap = A;
#pragma unroll
    for (int i = 0; i < 8; i++) Ap *= Ap;   // A^256
    float s = 0.f;
#pragma unroll
    for (int c = 0; c < NCHUNK; c++) {
        s = fmaf(Ap, s, partial[(b * NCHUNK + c) * DIM + d]);
        carry[(b * NCHUNK + c) * DIM + d] = s;
    }
}

// replay each chunk from the correct carry; emit y as fp16
__global__ __launch_bounds__(256) void scan_apply(
    const float* __restrict__ h, const float* __restrict__ a,
    const float* __restrict__ bgate, const float* __restrict__ carry,
    __half* __restrict__ yf)
{
    const int d = blockIdx.x * blockDim.x + threadIdx.x;
    const int c = blockIdx.y;
    const int b = blockIdx.z;
    const float A  = 1.f / (1.f + expf(-a[d]));
    const float bb = bgate[d];

    float s = (c == 0) ? 0.f : carry[(b * NCHUNK + (c - 1)) * DIM + d];

    const size_t off = (size_t)(b * SEQ + c * CHUNK) * DIM + d;
    const float* hp = h + off;
#pragma unroll 8
    for (int t = 0; t < CHUNK; t++) {
        s = fmaf(A, s, bb * hp[(size_t)t * DIM]);
        yf[off + (size_t)t * DIM] = __float2half_rn(s);
    }
}

// ---------------------------------------------------------------------------
extern "C" void kernel_launch(void* const* d_in, const int* in_sizes, int n_in,
                              void* d_out, int out_size)
{
    const float* x     = (const float*)d_in[0];
    const float* w_in  = (const float*)d_in[1];
    const float* b_in  = (const float*)d_in[2];
    const float* a     = (const float*)d_in[3];
    const float* bg    = (const float*)d_in[4];
    const float* w_out = (const float*)d_in[5];
    const float* b_out = (const float*)d_in[6];
    float* out = (float*)d_out;

    float *h, *partial, *carry;
    __half *xf, *wif, *wof;
    cudaGetSymbolAddress((void**)&h, g_h);
    cudaGetSymbolAddress((void**)&xf, g_xf);
    cudaGetSymbolAddress((void**)&wif, g_wif);
    cudaGetSymbolAddress((void**)&wof, g_wof);
    cudaGetSymbolAddress((void**)&partial, g_partial);
    cudaGetSymbolAddress((void**)&carry, g_carry);

    cudaFuncSetAttribute(gemm_fp16, cudaFuncAttributeMaxDynamicSharedMemorySize, GEMM_SMEM);

    // convert inputs to fp16
    {
        int n4 = MTOT * DIM / 4;
        to_fp16<<<n4 / 256, 256>>>((const float4*)x, (__half2*)xf, n4);
        int w4 = DIM * DIM / 4;
        to_fp16<<<w4 / 256, 256>>>((const float4*)w_in, (__half2*)wif, w4);
        to_fp16<<<w4 / 256, 256>>>((const float4*)w_out, (__half2*)wof, w4);
    }

    // GEMM 1: h = x @ w_in^T + b_in
    {
        dim3 grid(DIM / GBN, MTOT / GBM);
        gemm_fp16<<<grid, NTHREADS, GEMM_SMEM>>>(xf, wif, b_in, h);
    }

    // scan; scan_apply writes fp16 y into xf (reuse)
    {
        dim3 g1(DIM / 256, NCHUNK, BATCH);
        scan_partial<<<g1, 256>>>(h, a, bg, partial);
        dim3 g2(DIM / 256, BATCH);
        scan_carries<<<g2, 256>>>(partial, a, carry);
        dim3 g3(DIM / 256, NCHUNK, BATCH);
        scan_apply<<<g3, 256>>>(h, a, bg, carry, xf);
    }

    // GEMM 2: out = y @ w_out^T + b_out
    {
        dim3 grid(DIM / GBN, MTOT / GBM);
        gemm_fp16<<<grid, NTHREADS, GEMM_SMEM>>>(xf, wof, b_out, out);
    }
}

// round 13
// speedup vs baseline: 10.1188x; 1.1444x over previous
#include <cuda_runtime.h>
#include <cuda_fp16.h>
#include <cstdint>
#include <math.h>

#define DIM    1024
#define BATCH  4
#define SEQ    8192
#define MTOT   (BATCH * SEQ)      // 32768
#define CHUNK  256
#define NCHUNK (SEQ / CHUNK)      // 32

// ---------------- scratch (device globals; no allocs allowed) ----------------
__device__ __half g_h[MTOT * DIM];          // in_proj output (fp16)
__device__ __half g_xf[MTOT * DIM];         // x as fp16, later y as fp16
__device__ __half g_wif[DIM * DIM];         // w_in fp16
__device__ __half g_wof[DIM * DIM];         // w_out fp16
__device__ float  g_partial[BATCH * NCHUNK * DIM];
__device__ float  g_carry[BATCH * NCHUNK * DIM];

// ---------------- PTX helpers (base ISA only) ----------
__device__ __forceinline__ uint32_t smem_u32(const void* p) {
    uint32_t a;
    asm("{ .reg .u64 t; cvta.to.shared.u64 t, %1; cvt.u32.u64 %0, t; }" : "=r"(a) : "l"(p));
    return a;
}
__device__ __forceinline__ void cp16(uint32_t saddr, const void* gaddr) {
    asm volatile("cp.async.cg.shared.global [%0], [%1], 16;" :: "r"(saddr), "l"(gaddr) : "memory");
}
__device__ __forceinline__ void ldsm4(uint32_t& r0, uint32_t& r1, uint32_t& r2, uint32_t& r3,
                                      uint32_t addr) {
    asm volatile("ldmatrix.sync.aligned.m8n8.x4.shared.b16 {%0,%1,%2,%3}, [%4];"
                 : "=r"(r0), "=r"(r1), "=r"(r2), "=r"(r3) : "r"(addr));
}
__device__ __forceinline__ void mma16816(float* d, const uint32_t* a, const uint32_t* b) {
    asm volatile(
        "mma.sync.aligned.m16n8k16.row.col.f32.f16.f16.f32 "
        "{%0,%1,%2,%3}, {%4,%5,%6,%7}, {%8,%9}, {%0,%1,%2,%3};"
        : "+f"(d[0]), "+f"(d[1]), "+f"(d[2]), "+f"(d[3])
        : "r"(a[0]), "r"(a[1]), "r"(a[2]), "r"(a[3]), "r"(b[0]), "r"(b[1]));
}

// ---------------- GEMM: C[m,n] = A[m,:]·B[n,:] + bias[n]   (fp16 in)
// CTA tile 128x128, BK=64, 256 threads / 8 warps (32x64 each), 3-stage
// cp.async pipeline, 2 CTAs per SM. Rows padded to 144B (banks 4r mod 32:
// conflict-free ldmatrix). 16 k-iters -> half the barrier overhead of BK=32.
// ----------------------------------------------------------------------------
#define GBM 128
#define GBN 128
#define GBK 64
#define KITERS (DIM / GBK)          // 16
#define ROWB   144                  // 64 fp16 = 128B + 16B pad
#define A_O    0
#define B_O    (GBM * ROWB)                     // 18432
#define STAGE_B ((GBM + GBN) * ROWB)            // 36864
#define NSTAGE 3
#define GEMM_SMEM (NSTAGE * STAGE_B)            // 110592
#define NTHREADS 256

__device__ __forceinline__ void load_stage(
    uint32_t sstage, const char* pA, const char* pB, int kbyte, int tid)
{
    // A: 128 rows x 8 x 16B chunks = 1024 chunks (4 per thread)
#pragma unroll
    for (int j = 0; j < 4; j++) {
        int id = tid + j * NTHREADS;            // 0..1023
        int row = id >> 3, c = id & 7;
        cp16(sstage + A_O + row * ROWB + c * 16,
             pA + (size_t)row * 2048 + kbyte + c * 16);
    }
    // B: 128 rows x 8 chunks = 1024 chunks (4 per thread)
#pragma unroll
    for (int j = 0; j < 4; j++) {
        int id = tid + j * NTHREADS;
        int row = id >> 3, c = id & 7;
        cp16(sstage + B_O + row * ROWB + c * 16,
             pB + (size_t)row * 2048 + kbyte + c * 16);
    }
}

template <typename OutT>
__global__ __launch_bounds__(NTHREADS, 2)
void gemm_fp16(const __half* __restrict__ A, const __half* __restrict__ B,
               const float* __restrict__ bias, OutT* __restrict__ C)
{
    extern __shared__ char smem[];
    const uint32_t sbase = smem_u32(smem);
    const int tid = threadIdx.x, wid = tid >> 5, lane = tid & 31;
    const int bn = blockIdx.x * GBN;
    const int bm = blockIdx.y * GBM;
    const int wm = wid & 3;            // 0..3 -> 32-row slab
    const int wn = wid >> 2;           // 0..1 -> 64-col slab

    const char* pA = (const char*)A + (size_t)bm * 2048;
    const char* pB = (const char*)B + (size_t)bn * 2048;

    float acc[2][8][4];
#pragma unroll
    for (int i = 0; i < 2; i++)
#pragma unroll
        for (int j = 0; j < 8; j++)
#pragma unroll
            for (int r = 0; r < 4; r++) acc[i][j][r] = 0.f;

    const uint32_t laneA = (uint32_t)(lane & 15) * ROWB + (uint32_t)(lane >> 4) * 16;
    const uint32_t laneB = (uint32_t)((lane & 7) + ((lane >> 4) << 3)) * ROWB
                         + (uint32_t)((lane >> 3) & 1) * 16;

    // prologue: stages 0,1
    load_stage(sbase + 0 * STAGE_B, pA, pB, 0, tid);
    asm volatile("cp.async.commit_group;" ::: "memory");
    load_stage(sbase + 1 * STAGE_B, pA, pB, GBK * 2, tid);
    asm volatile("cp.async.commit_group;" ::: "memory");

    int slot = 0;
    for (int i = 0; i < KITERS; i++) {
        if (i + 1 < KITERS)
            asm volatile("cp.async.wait_group 1;" ::: "memory");
        else
            asm volatile("cp.async.wait_group 0;" ::: "memory");
        __syncthreads();

        if (i + 2 < KITERS) {
            int ws = slot + 2; if (ws >= NSTAGE) ws -= NSTAGE;
            load_stage(sbase + ws * STAGE_B, pA, pB, (i + 2) * (GBK * 2), tid);
            asm volatile("cp.async.commit_group;" ::: "memory");
        }

        const uint32_t sg = sbase + slot * STAGE_B;
        const uint32_t aBase = sg + A_O + (uint32_t)wm * 32 * ROWB;
        const uint32_t bBase = sg + B_O + (uint32_t)wn * 64 * ROWB;

#pragma unroll
        for (int ks = 0; ks < 4; ks++) {
            const uint32_t ko = (uint32_t)ks * 32;
            uint32_t af[2][4];
#pragma unroll
            for (int mi = 0; mi < 2; mi++)
                ldsm4(af[mi][0], af[mi][1], af[mi][2], af[mi][3],
                      aBase + (uint32_t)mi * 16 * ROWB + ko + laneA);
#pragma unroll
            for (int nh = 0; nh < 4; nh++) {
                uint32_t b0[2], b1[2];
                ldsm4(b0[0], b0[1], b1[0], b1[1],
                      bBase + (uint32_t)nh * 16 * ROWB + ko + laneB);
#pragma unroll
                for (int mi = 0; mi < 2; mi++) {
                    mma16816(acc[mi][2 * nh],     af[mi], b0);
                    mma16816(acc[mi][2 * nh + 1], af[mi], b1);
                }
            }
        }

        if (++slot == NSTAGE) slot = 0;
    }

    // epilogue: bias + store (fp32 or fp16 depending on OutT)
#pragma unroll
    for (int mi = 0; mi < 2; mi++) {
        int r0 = bm + wm * 32 + mi * 16 + (lane >> 2);
#pragma unroll
        for (int ni = 0; ni < 8; ni++) {
            int cix = bn + wn * 64 + ni * 8 + (lane & 3) * 2;
            float2 bv = *(const float2*)(bias + cix);
            float2 o0, o1;
            o0.x = acc[mi][ni][0] + bv.x; o0.y = acc[mi][ni][1] + bv.y;
            o1.x = acc[mi][ni][2] + bv.x; o1.y = acc[mi][ni][3] + bv.y;
            if (sizeof(OutT) == 4) {
                *(float2*)((float*)C + (size_t)r0 * DIM + cix) = o0;
                *(float2*)((float*)C + (size_t)(r0 + 8) * DIM + cix) = o1;
            } else {
                *(__half2*)((__half*)C + (size_t)r0 * DIM + cix) = __floats2half2_rn(o0.x, o0.y);
                *(__half2*)((__half*)C + (size_t)(r0 + 8) * DIM + cix) = __floats2half2_rn(o1.x, o1.y);
            }
        }
    }
}

// ---------------- fp32 -> fp16 convert ----------------
__global__ __launch_bounds__(256) void to_fp16(
    const float4* __restrict__ in, __half2* __restrict__ out, int n4)
{
    int i = blockIdx.x * blockDim.x + threadIdx.x;
    if (i >= n4) return;
    float4 v = in[i];
    out[2 * i + 0] = __floats2half2_rn(v.x, v.y);
    out[2 * i + 1] = __floats2half2_rn(v.z, v.w);
}

// ---------------- scan (3-stage chunked linear recurrence, fp16 h) ----------
__global__ __launch_bounds__(256) void scan_partial(
    const __half* __restrict__ h, const float* __restrict__ a,
    const float* __restrict__ bgate, float* __restrict__ partial)
{
    const int d = blockIdx.x * blockDim.x + threadIdx.x;
    const int c = blockIdx.y;
    const int b = blockIdx.z;
    const float A  = 1.f / (1.f + expf(-a[d]));
    const float bb = bgate[d];
    const __half* hp = h + ((size_t)(b * SEQ + c * CHUNK)) * DIM + d;
    float s = 0.f;
#pragma unroll 8
    for (int t = 0; t < CHUNK; t++)
        s = fmaf(A, s, bb * __half2float(hp[(size_t)t * DIM]));
    partial[(b * NCHUNK + c) * DIM + d] = s;
}

__global__ __launch_bounds__(256) void scan_carries(
    const float* __restrict__ partial, const float* __restrict__ a,
    float* __restrict__ carry)
{
    const int d = blockIdx.x * blockDim.x + threadIdx.x;
    const int b = blockIdx.y;
    const float A = 1.f / (1.f + expf(-a[d]));
    float Ap = A;
#pragma unroll
    for (int i = 0; i < 8; i++) Ap *= Ap;   // A^256
    float s = 0.f;
#pragma unroll
    for (int c = 0; c < NCHUNK; c++) {
        s = fmaf(Ap, s, partial[(b * NCHUNK + c) * DIM + d]);
        carry[(b * NCHUNK + c) * DIM + d] = s;
    }
}

// replay each chunk from the correct carry; emit y as fp16
__global__ __launch_bounds__(256) void scan_apply(
    const __half* __restrict__ h, const float* __restrict__ a,
    const float* __restrict__ bgate, const float* __restrict__ carry,
    __half* __restrict__ yf)
{
    const int d = blockIdx.x * blockDim.x + threadIdx.x;
    const int c = blockIdx.y;
    const int b = blockIdx.z;
    const float A  = 1.f / (1.f + expf(-a[d]));
    const float bb = bgate[d];

    float s = (c == 0) ? 0.f : carry[(b * NCHUNK + (c - 1)) * DIM + d];

    const size_t off = (size_t)(b * SEQ + c * CHUNK) * DIM + d;
    const __half* hp = h + off;
#pragma unroll 8
    for (int t = 0; t < CHUNK; t++) {
        s = fmaf(A, s, bb * __half2float(hp[(size_t)t * DIM]));
        yf[off + (size_t)t * DIM] = __float2half_rn(s);
    }
}

// ---------------------------------------------------------------------------
extern "C" void kernel_launch(void* const* d_in, const int* in_sizes, int n_in,
                              void* d_out, int out_size)
{
    const float* x     = (const float*)d_in[0];
    const float* w_in  = (const float*)d_in[1];
    const float* b_in  = (const float*)d_in[2];
    const float* a     = (const float*)d_in[3];
    const float* bg    = (const float*)d_in[4];
    const float* w_out = (const float*)d_in[5];
    const float* b_out = (const float*)d_in[6];
    float* out = (float*)d_out;

    float *partial, *carry;
    __half *h, *xf, *wif, *wof;
    cudaGetSymbolAddress((void**)&h, g_h);
    cudaGetSymbolAddress((void**)&xf, g_xf);
    cudaGetSymbolAddress((void**)&wif, g_wif);
    cudaGetSymbolAddress((void**)&wof, g_wof);
    cudaGetSymbolAddress((void**)&partial, g_partial);
    cudaGetSymbolAddress((void**)&carry, g_carry);

    cudaFuncSetAttribute(gemm_fp16<__half>, cudaFuncAttributeMaxDynamicSharedMemorySize, GEMM_SMEM);
    cudaFuncSetAttribute(gemm_fp16<float>,  cudaFuncAttributeMaxDynamicSharedMemorySize, GEMM_SMEM);

    // convert inputs to fp16
    {
        int n4 = MTOT * DIM / 4;
        to_fp16<<<n4 / 256, 256>>>((const float4*)x, (__half2*)xf, n4);
        int w4 = DIM * DIM / 4;
        to_fp16<<<w4 / 256, 256>>>((const float4*)w_in, (__half2*)wif, w4);
        to_fp16<<<w4 / 256, 256>>>((const float4*)w_out, (__half2*)wof, w4);
    }

    // GEMM 1: h = x @ w_in^T + b_in   (fp16 output)
    {
        dim3 grid(DIM / GBN, MTOT / GBM);
        gemm_fp16<__half><<<grid, NTHREADS, GEMM_SMEM>>>(xf, wif, b_in, h);
    }

    // scan; scan_apply writes fp16 y into xf (reuse)
    {
        dim3 g1(DIM / 256, NCHUNK, BATCH);
        scan_partial<<<g1, 256>>>(h, a, bg, partial);
        dim3 g2(DIM / 256, BATCH);
        scan_carries<<<g2, 256>>>(partial, a, carry);
        dim3 g3(DIM / 256, NCHUNK, BATCH);
        scan_apply<<<g3, 256>>>(h, a, bg, carry, xf);
    }

    // GEMM 2: out = y @ w_out^T + b_out   (fp32 output)
    {
        dim3 grid(DIM / GBN, MTOT / GBM);
        gemm_fp16<float><<<grid, NTHREADS, GEMM_SMEM>>>(xf, wof, b_out, out);
    }
}